// round 3
// baseline (speedup 1.0000x reference)
#include <cuda_runtime.h>
#include <math.h>

// Problem constants
#define NTOK   262144          // 4096 * 64 tokens
#define CDIM   256
#define NH     8
#define HD     32
#define NWIN   64
#define MAX_LOGIT 4.6051701859880914f   // log(100)

// ---------------------------------------------------------------------------
// Scratch (static device globals — allocation-guard safe)
// ---------------------------------------------------------------------------
__device__ float g_qkv[(size_t)NTOK * 768];     // raw qkv = x @ qkv_w^T + b
__device__ float g_q[(size_t)NTOK * CDIM];      // [B,H,N,hd] rope+normalized
__device__ float g_k[(size_t)NTOK * CDIM];
__device__ float g_v[(size_t)NTOK * CDIM];
__device__ float g_ao[(size_t)NTOK * CDIM];     // attention out, [B,N,C]

// ---------------------------------------------------------------------------
// GEMM: C[M,N] = A[M,K] @ W[N,K]^T + bias    (both K-contiguous, row-major)
// BM=128, BN=64, BK=16, 256 threads, 8x4 per-thread tile.
// ---------------------------------------------------------------------------
template<int N, int K>
__global__ __launch_bounds__(256)
void gemm_bias_kernel(const float* __restrict__ A,
                      const float* __restrict__ W,
                      const float* __restrict__ bias,
                      float* __restrict__ C)
{
    __shared__ float As[16][128];
    __shared__ float Bs[16][64];

    const int t  = threadIdx.x;
    const int tx = t & 15;          // 16 col-groups of 4
    const int ty = t >> 4;          // 16 row-groups of 8
    const int bx = blockIdx.x;      // N / 64
    const int by = blockIdx.y;      // M / 128

    float acc[8][4];
#pragma unroll
    for (int i = 0; i < 8; i++)
#pragma unroll
        for (int j = 0; j < 4; j++) acc[i][j] = 0.f;

    const float* Ab = A + (size_t)by * 128 * K;
    const float* Wb = W + (size_t)bx * 64 * K;

    for (int kt = 0; kt < K; kt += 16) {
        // A tile: 128x16 = 512 float4, 2 per thread (store transposed)
#pragma unroll
        for (int u = 0; u < 2; u++) {
            int idx = t + u * 256;
            int row = idx >> 2;
            int cv  = idx & 3;
            float4 av = *(const float4*)(Ab + (size_t)row * K + kt + cv * 4);
            As[cv * 4 + 0][row] = av.x;
            As[cv * 4 + 1][row] = av.y;
            As[cv * 4 + 2][row] = av.z;
            As[cv * 4 + 3][row] = av.w;
        }
        // W tile: 64x16 = 256 float4, 1 per thread
        {
            int row = t >> 2;
            int cv  = t & 3;
            float4 wv = *(const float4*)(Wb + (size_t)row * K + kt + cv * 4);
            Bs[cv * 4 + 0][row] = wv.x;
            Bs[cv * 4 + 1][row] = wv.y;
            Bs[cv * 4 + 2][row] = wv.z;
            Bs[cv * 4 + 3][row] = wv.w;
        }
        __syncthreads();

#pragma unroll
        for (int k = 0; k < 16; k++) {
            float a[8], b[4];
#pragma unroll
            for (int i = 0; i < 8; i++) a[i] = As[k][ty * 8 + i];
#pragma unroll
            for (int j = 0; j < 4; j++) b[j] = Bs[k][tx * 4 + j];
#pragma unroll
            for (int i = 0; i < 8; i++)
#pragma unroll
                for (int j = 0; j < 4; j++)
                    acc[i][j] += a[i] * b[j];
        }
        __syncthreads();
    }

    const int col = bx * 64 + tx * 4;
    float4 bv = *(const float4*)(bias + col);
#pragma unroll
    for (int i = 0; i < 8; i++) {
        size_t row = (size_t)by * 128 + ty * 8 + i;
        float4 o;
        o.x = acc[i][0] + bv.x;
        o.y = acc[i][1] + bv.y;
        o.z = acc[i][2] + bv.z;
        o.w = acc[i][3] + bv.w;
        *(float4*)(C + row * N + col) = o;
    }
}

// ---------------------------------------------------------------------------
// RoPE + L2-normalize + scatter to [B,H,N,hd]. One warp per (token, head).
// ---------------------------------------------------------------------------
__global__ __launch_bounds__(256)
void rope_norm_kernel()
{
    const int lane = threadIdx.x & 31;
    const int warp = threadIdx.x >> 5;
    const int gw   = blockIdx.x * 8 + warp;     // (token, head) id
    const int row  = gw >> 3;                   // token
    const int h    = gw & 7;
    const int n    = row & 63;

    size_t base = (size_t)row * 768 + h * 32 + lane;
    float qv = g_qkv[base];
    float kv = g_qkv[base + 256];
    float vv = g_qkv[base + 512];

    // rope angles: inv_freq[i] = 10000^(-i/16), t = n + VIEW_ID*VIEW_OFFSET
    const float tpos = (float)n + 0.1f;
    const int   i    = lane & 15;
    // log2(10000)/16 = 0.83048202372...
    float invf = exp2f(-(float)i * 0.8304820237218406f);
    float ang  = tpos * invf;
    float s, c;
    sincosf(ang, &s, &c);

    float qo = __shfl_xor_sync(0xffffffffu, qv, 16);
    float ko = __shfl_xor_sync(0xffffffffu, kv, 16);
    float qr = (lane < 16) ? (qv * c - qo * s) : (qo * s + qv * c);
    float kr = (lane < 16) ? (kv * c - ko * s) : (ko * s + kv * c);

    // normalize
    float nq = qr * qr, nk = kr * kr;
#pragma unroll
    for (int o = 16; o; o >>= 1) {
        nq += __shfl_xor_sync(0xffffffffu, nq, o);
        nk += __shfl_xor_sync(0xffffffffu, nk, o);
    }
    qr /= fmaxf(sqrtf(nq), 1e-12f);
    kr /= fmaxf(sqrtf(nk), 1e-12f);

    // scatter to [b][h][n][d]
    const int b = row >> 6;
    size_t oidx = ((size_t)(b * 8 + h) * 64 + n) * 32 + lane;
    g_q[oidx] = qr;
    g_k[oidx] = kr;
    g_v[oidx] = vv;
}

// ---------------------------------------------------------------------------
// Attention: one block per (b, h). 256 threads = 8 warps, 8 rows per warp.
// ---------------------------------------------------------------------------
__global__ __launch_bounds__(256)
void attn_kernel(const float* __restrict__ mask, const float* __restrict__ ls)
{
    __shared__ float sq[64 * 32];
    __shared__ float skT[32 * 66];      // kT[d][c] padded to 66 (conflict-free)
    __shared__ float sv[64 * 32];
    __shared__ float pbuf[8][64];

    const int bid  = blockIdx.x;
    const int b    = bid >> 3;
    const int h    = bid & 7;
    const int w    = b & (NWIN - 1);
    const int t    = threadIdx.x;
    const int lane = t & 31;
    const int warp = t >> 5;

    const size_t base = (size_t)bid * 2048;   // 64*32 per (b,h)

    // load q, v (float4), kT (transposed scalar)
    const float4* q4 = (const float4*)(g_q + base);
    const float4* v4 = (const float4*)(g_v + base);
    float4* sq4 = (float4*)sq;
    float4* sv4 = (float4*)sv;
#pragma unroll
    for (int u = 0; u < 2; u++) {
        sq4[t + u * 256] = q4[t + u * 256];
        sv4[t + u * 256] = v4[t + u * 256];
    }
    const float* kp = g_k + base;
#pragma unroll
    for (int u = 0; u < 8; u++) {
        int idx = t + u * 256;
        int r = idx >> 5, d = idx & 31;
        skT[d * 66 + r] = kp[idx];
    }
    const float scale = expf(fminf(ls[h], MAX_LOGIT));
    __syncthreads();

    const float2* skT2 = (const float2*)skT;               // [d][33] float2
    const float2* m2   = (const float2*)(mask + (size_t)w * 4096);

    for (int rr = 0; rr < 8; rr++) {
        const int r = warp * 8 + rr;
        float s0 = 0.f, s1 = 0.f;
        const float4* qrow = (const float4*)(sq + r * 32);
#pragma unroll
        for (int d4 = 0; d4 < 8; d4++) {
            float4 qv = qrow[d4];
            float2 k0 = skT2[(d4 * 4 + 0) * 33 + lane];
            float2 k1 = skT2[(d4 * 4 + 1) * 33 + lane];
            float2 k2 = skT2[(d4 * 4 + 2) * 33 + lane];
            float2 k3 = skT2[(d4 * 4 + 3) * 33 + lane];
            s0 += qv.x * k0.x + qv.y * k1.x + qv.z * k2.x + qv.w * k3.x;
            s1 += qv.x * k0.y + qv.y * k1.y + qv.z * k2.y + qv.w * k3.y;
        }
        float2 mv = m2[r * 32 + lane];
        s0 = s0 * scale + mv.x;
        s1 = s1 * scale + mv.y;

        // softmax across 64 cols (2 per lane)
        float mx = fmaxf(s0, s1);
#pragma unroll
        for (int o = 16; o; o >>= 1) mx = fmaxf(mx, __shfl_xor_sync(0xffffffffu, mx, o));
        float e0 = expf(s0 - mx), e1 = expf(s1 - mx);
        float sum = e0 + e1;
#pragma unroll
        for (int o = 16; o; o >>= 1) sum += __shfl_xor_sync(0xffffffffu, sum, o);
        float inv = 1.f / sum;
        ((float2*)pbuf[warp])[lane] = make_float2(e0 * inv, e1 * inv);
        __syncwarp();

        // O row: lane = head-dim d
        float acc = 0.f;
        const float4* p4 = (const float4*)pbuf[warp];
#pragma unroll
        for (int m4 = 0; m4 < 16; m4++) {
            float4 pv = p4[m4];
            acc += pv.x * sv[(m4 * 4 + 0) * 32 + lane]
                 + pv.y * sv[(m4 * 4 + 1) * 32 + lane]
                 + pv.z * sv[(m4 * 4 + 2) * 32 + lane]
                 + pv.w * sv[(m4 * 4 + 3) * 32 + lane];
        }
        // write to [b][n][h*32+d]
        g_ao[((size_t)b * 64 + r) * 256 + h * 32 + lane] = acc;
        __syncwarp();
    }
}

// ---------------------------------------------------------------------------
// Launch
// ---------------------------------------------------------------------------
extern "C" void kernel_launch(void* const* d_in, const int* in_sizes, int n_in,
                              void* d_out, int out_size)
{
    const float* x      = (const float*)d_in[0];
    const float* mask   = (const float*)d_in[1];
    const float* qkv_w  = (const float*)d_in[2];
    const float* qkv_b  = (const float*)d_in[3];
    const float* proj_w = (const float*)d_in[4];
    const float* proj_b = (const float*)d_in[5];
    const float* ls     = (const float*)d_in[6];

    float *p_qkv = nullptr, *p_ao = nullptr;
    cudaGetSymbolAddress((void**)&p_qkv, g_qkv);
    cudaGetSymbolAddress((void**)&p_ao,  g_ao);

    // 1) QKV GEMM: [262144,256] @ [768,256]^T
    gemm_bias_kernel<768, 256><<<dim3(768 / 64, NTOK / 128), 256>>>(
        x, qkv_w, qkv_b, p_qkv);

    // 2) RoPE + normalize + scatter (2M warps)
    rope_norm_kernel<<<NTOK * 8 / 8, 256>>>();

    // 3) attention per (b, h)
    attn_kernel<<<4096 * 8, 256>>>(mask, ls);

    // 4) proj GEMM: [262144,256] @ [256,256]^T -> out
    gemm_bias_kernel<256, 256><<<dim3(256 / 64, NTOK / 128), 256>>>(
        p_ao, proj_w, proj_b, (float*)d_out);
}

// round 6
// speedup vs baseline: 1.5875x; 1.5875x over previous
#include <cuda_runtime.h>
#include <cuda_bf16.h>
#include <math.h>
#include <stdint.h>

// Problem constants
#define NTOK   262144          // 4096 * 64 tokens
#define CDIM   256
#define NH     8
#define HD     32
#define NWIN   64
#define MAX_LOGIT 4.6051701859880914f   // log(100)

// ---------------------------------------------------------------------------
// Scratch (static device globals — allocation-guard safe)
// ---------------------------------------------------------------------------
__device__ __align__(16) __nv_bfloat16 g_xhi[(size_t)NTOK * CDIM];
__device__ __align__(16) __nv_bfloat16 g_xlo[(size_t)NTOK * CDIM];
__device__ __align__(16) __nv_bfloat16 g_wqhi[768 * 256];
__device__ __align__(16) __nv_bfloat16 g_wqlo[768 * 256];
__device__ __align__(16) __nv_bfloat16 g_wphi[256 * 256];
__device__ __align__(16) __nv_bfloat16 g_wplo[256 * 256];
__device__ __align__(16) float g_qkv[(size_t)NTOK * 768];
__device__ __align__(16) float g_q[(size_t)NTOK * CDIM];
__device__ __align__(16) float g_k[(size_t)NTOK * CDIM];
__device__ __align__(16) float g_v[(size_t)NTOK * CDIM];
__device__ __align__(16) __nv_bfloat16 g_aohi[(size_t)NTOK * CDIM];
__device__ __align__(16) __nv_bfloat16 g_aolo[(size_t)NTOK * CDIM];

// ---------------------------------------------------------------------------
// Helpers (base-target PTX only: cp.async, ldmatrix, mma.sync)
// ---------------------------------------------------------------------------
__device__ __forceinline__ uint32_t smem_u32(const void* p) {
    uint32_t a;
    asm("{ .reg .u64 t; cvta.to.shared.u64 t, %1; cvt.u32.u64 %0, t; }"
        : "=r"(a) : "l"(p));
    return a;
}
#define CP_ASYNC16(dst, src) \
    asm volatile("cp.async.cg.shared.global [%0], [%1], 16;" \
                 :: "r"(dst), "l"(src) : "memory")
#define CP_COMMIT() asm volatile("cp.async.commit_group;" ::: "memory")
#define CP_WAIT(n)  asm volatile("cp.async.wait_group %0;" :: "n"(n) : "memory")

__device__ __forceinline__ void ldsm4(uint32_t& r0, uint32_t& r1,
                                      uint32_t& r2, uint32_t& r3, uint32_t addr) {
    asm volatile("ldmatrix.sync.aligned.m8n8.x4.shared.b16 {%0,%1,%2,%3}, [%4];"
                 : "=r"(r0), "=r"(r1), "=r"(r2), "=r"(r3) : "r"(addr));
}
__device__ __forceinline__ void mma_bf16(float& d0, float& d1, float& d2, float& d3,
                                         uint32_t a0, uint32_t a1, uint32_t a2, uint32_t a3,
                                         uint32_t b0, uint32_t b1) {
    asm volatile("mma.sync.aligned.m16n8k16.row.col.f32.bf16.bf16.f32 "
                 "{%0,%1,%2,%3}, {%4,%5,%6,%7}, {%8,%9}, {%0,%1,%2,%3};"
                 : "+f"(d0), "+f"(d1), "+f"(d2), "+f"(d3)
                 : "r"(a0), "r"(a1), "r"(a2), "r"(a3), "r"(b0), "r"(b1));
}

// ---------------------------------------------------------------------------
// fp32 -> (hi, lo) bf16 split
// ---------------------------------------------------------------------------
__global__ __launch_bounds__(256)
void split_kernel(const float* __restrict__ src,
                  __nv_bfloat16* __restrict__ hi,
                  __nv_bfloat16* __restrict__ lo, int n4)
{
    int i = blockIdx.x * 256 + threadIdx.x;
    if (i >= n4) return;
    float4 v = ((const float4*)src)[i];
    __nv_bfloat16 h0 = __float2bfloat16(v.x);
    __nv_bfloat16 h1 = __float2bfloat16(v.y);
    __nv_bfloat16 h2 = __float2bfloat16(v.z);
    __nv_bfloat16 h3 = __float2bfloat16(v.w);
    __nv_bfloat16 l0 = __float2bfloat16(v.x - __bfloat162float(h0));
    __nv_bfloat16 l1 = __float2bfloat16(v.y - __bfloat162float(h1));
    __nv_bfloat16 l2 = __float2bfloat16(v.z - __bfloat162float(h2));
    __nv_bfloat16 l3 = __float2bfloat16(v.w - __bfloat162float(h3));
    __nv_bfloat162 ha = {h0, h1}, hb = {h2, h3};
    __nv_bfloat162 la = {l0, l1}, lb = {l2, l3};
    uint2 ho, loo;
    ho.x = *(uint32_t*)&ha; ho.y = *(uint32_t*)&hb;
    loo.x = *(uint32_t*)&la; loo.y = *(uint32_t*)&lb;
    ((uint2*)hi)[i] = ho;
    ((uint2*)lo)[i] = loo;
}

// ---------------------------------------------------------------------------
// HMMA bf16 split GEMM:  C[M, Ncols] = A[M,256] @ W[Ncols,256]^T + bias
// A, W given as hi/lo bf16 (K-contiguous, K=256).
// Virtual K = 768 = 24 chunks of BK=32:
//   chunks 0-7:  Ahi x Whi,  8-15: Ahi x Wlo,  16-23: Alo x Whi.
// Block tile 128x128, 8 warps (4x2), warp tile 32x64, m16n8k16.
// Smem rows padded to 80B (5 x 16B chunks) => conflict-free ldmatrix.
// ---------------------------------------------------------------------------
#define BKB   80          // padded bytes per 32-element bf16 row
#define STG_A 10240       // 128 * 80
#define STG_B 10240

__global__ __launch_bounds__(256)
void gemm_mma_kernel(const __nv_bfloat16* __restrict__ Ahi,
                     const __nv_bfloat16* __restrict__ Alo,
                     const __nv_bfloat16* __restrict__ Whi,
                     const __nv_bfloat16* __restrict__ Wlo,
                     const float* __restrict__ bias,
                     float* __restrict__ C, int Ncols)
{
    __shared__ __align__(16) char smem[2 * STG_A + 2 * STG_B];
    const uint32_t sb  = smem_u32(smem);
    const uint32_t sbA = sb;                  // stage s at sb + s*STG_A
    const uint32_t sbB = sb + 2 * STG_A;      // stage s at sbB + s*STG_B

    const int t      = threadIdx.x;
    const int lane   = t & 31;
    const int wid    = t >> 5;
    const int warp_m = wid >> 1;              // 0..3
    const int warp_n = wid & 1;               // 0..1
    const int bx     = blockIdx.x;            // Ncols / 128
    const int by     = blockIdx.y;            // M / 128

    // per-thread gmem load coords: 2 rows-chunks for A, 2 for B per stage
    const int ldr = t >> 2;                   // 0..63
    const int ldc = t & 3;                    // 16B chunk 0..3

    float acc[2][8][4];
#pragma unroll
    for (int i = 0; i < 2; i++)
#pragma unroll
        for (int j = 0; j < 8; j++)
#pragma unroll
            for (int q = 0; q < 4; q++) acc[i][j][q] = 0.f;

    const size_t Aoff = (size_t)by * 128 * 256;
    const size_t Woff = (size_t)bx * 128 * 256;

    // ldmatrix per-lane smem addresses (byte offsets within a stage)
    const uint32_t a_row  = lane & 15;            // m row within m16 tile
    const uint32_t a_kh   = (lane >> 4) & 1;      // k-half (16B)
    const uint32_t b_row  = (lane & 7) | ((lane >> 4) << 3);  // n row within n16
    const uint32_t b_kh   = (lane >> 3) & 1;

#define LOAD_STAGE(c, s)                                                        \
    do {                                                                        \
        const __nv_bfloat16* As_ = ((c) < 16 ? Ahi : Alo) + Aoff + ((c) & 7) * 32; \
        const __nv_bfloat16* Ws_ = (((c) >= 8 && (c) < 16) ? Wlo : Whi) + Woff + ((c) & 7) * 32; \
        uint32_t dA = sbA + (s) * STG_A;                                        \
        uint32_t dB = sbB + (s) * STG_B;                                        \
        CP_ASYNC16(dA + ldr * BKB + ldc * 16,        As_ + (size_t)ldr * 256 + ldc * 8); \
        CP_ASYNC16(dA + (ldr + 64) * BKB + ldc * 16, As_ + (size_t)(ldr + 64) * 256 + ldc * 8); \
        CP_ASYNC16(dB + ldr * BKB + ldc * 16,        Ws_ + (size_t)ldr * 256 + ldc * 8); \
        CP_ASYNC16(dB + (ldr + 64) * BKB + ldc * 16, Ws_ + (size_t)(ldr + 64) * 256 + ldc * 8); \
        CP_COMMIT();                                                            \
    } while (0)

    LOAD_STAGE(0, 0);

    for (int c = 0; c < 24; ++c) {
        const int s = c & 1;
        if (c + 1 < 24) {
            LOAD_STAGE(c + 1, s ^ 1);
            CP_WAIT(1);
        } else {
            CP_WAIT(0);
        }
        __syncthreads();

        const uint32_t baseA = sbA + s * STG_A + (warp_m * 32 + a_row) * BKB + a_kh * 16;
        const uint32_t baseB = sbB + s * STG_B + (warp_n * 64 + b_row) * BKB + b_kh * 16;

#pragma unroll
        for (int ks = 0; ks < 2; ks++) {
            uint32_t b[4][4];
#pragma unroll
            for (int bn = 0; bn < 4; bn++)
                ldsm4(b[bn][0], b[bn][1], b[bn][2], b[bn][3],
                      baseB + bn * 16 * BKB + ks * 32);
#pragma unroll
            for (int im = 0; im < 2; im++) {
                uint32_t a0, a1, a2, a3;
                ldsm4(a0, a1, a2, a3, baseA + im * 16 * BKB + ks * 32);
#pragma unroll
                for (int bn = 0; bn < 4; bn++) {
                    mma_bf16(acc[im][2 * bn][0], acc[im][2 * bn][1],
                             acc[im][2 * bn][2], acc[im][2 * bn][3],
                             a0, a1, a2, a3, b[bn][0], b[bn][1]);
                    mma_bf16(acc[im][2 * bn + 1][0], acc[im][2 * bn + 1][1],
                             acc[im][2 * bn + 1][2], acc[im][2 * bn + 1][3],
                             a0, a1, a2, a3, b[bn][2], b[bn][3]);
                }
            }
        }
        __syncthreads();
    }

    // epilogue: add bias, fp32 stores
    const int qr = lane >> 2;
    const int qc = (lane & 3) * 2;
#pragma unroll
    for (int im = 0; im < 2; im++) {
        const int m0 = by * 128 + warp_m * 32 + im * 16 + qr;
#pragma unroll
        for (int nn = 0; nn < 8; nn++) {
            const int col = bx * 128 + warp_n * 64 + nn * 8 + qc;
            float2 bv = *(const float2*)(bias + col);
            float2 o0, o1;
            o0.x = acc[im][nn][0] + bv.x;
            o0.y = acc[im][nn][1] + bv.y;
            o1.x = acc[im][nn][2] + bv.x;
            o1.y = acc[im][nn][3] + bv.y;
            *(float2*)(C + (size_t)m0 * Ncols + col)       = o0;
            *(float2*)(C + (size_t)(m0 + 8) * Ncols + col) = o1;
        }
    }
}

// ---------------------------------------------------------------------------
// RoPE + L2-normalize + scatter to [B,H,N,hd]. One warp per (token, head).
// ---------------------------------------------------------------------------
__global__ __launch_bounds__(256)
void rope_norm_kernel()
{
    const int lane = threadIdx.x & 31;
    const int warp = threadIdx.x >> 5;
    const int gw   = blockIdx.x * 8 + warp;
    const int row  = gw >> 3;
    const int h    = gw & 7;
    const int n    = row & 63;

    size_t base = (size_t)row * 768 + h * 32 + lane;
    float qv = g_qkv[base];
    float kv = g_qkv[base + 256];
    float vv = g_qkv[base + 512];

    const float tpos = (float)n + 0.1f;
    const int   i    = lane & 15;
    float invf = exp2f(-(float)i * 0.8304820237218406f);
    float ang  = tpos * invf;
    float s, c;
    sincosf(ang, &s, &c);

    float qo = __shfl_xor_sync(0xffffffffu, qv, 16);
    float ko = __shfl_xor_sync(0xffffffffu, kv, 16);
    float qr = (lane < 16) ? (qv * c - qo * s) : (qo * s + qv * c);
    float kr = (lane < 16) ? (kv * c - ko * s) : (ko * s + kv * c);

    float nq = qr * qr, nk = kr * kr;
#pragma unroll
    for (int o = 16; o; o >>= 1) {
        nq += __shfl_xor_sync(0xffffffffu, nq, o);
        nk += __shfl_xor_sync(0xffffffffu, nk, o);
    }
    qr /= fmaxf(sqrtf(nq), 1e-12f);
    kr /= fmaxf(sqrtf(nk), 1e-12f);

    const int b = row >> 6;
    size_t oidx = ((size_t)(b * 8 + h) * 64 + n) * 32 + lane;
    g_q[oidx] = qr;
    g_k[oidx] = kr;
    g_v[oidx] = vv;
}

// ---------------------------------------------------------------------------
// Attention: one block per (b, h). 256 threads = 8 warps, 8 rows per warp.
// Epilogue writes bf16 hi/lo split of the output (feeds proj HMMA GEMM).
// ---------------------------------------------------------------------------
__global__ __launch_bounds__(256)
void attn_kernel(const float* __restrict__ mask, const float* __restrict__ ls)
{
    __shared__ float sq[64 * 32];
    __shared__ float skT[32 * 66];
    __shared__ float sv[64 * 32];
    __shared__ float pbuf[8][64];

    const int bid  = blockIdx.x;
    const int b    = bid >> 3;
    const int h    = bid & 7;
    const int w    = b & (NWIN - 1);
    const int t    = threadIdx.x;
    const int lane = t & 31;
    const int warp = t >> 5;

    const size_t base = (size_t)bid * 2048;

    const float4* q4 = (const float4*)(g_q + base);
    const float4* v4 = (const float4*)(g_v + base);
    float4* sq4 = (float4*)sq;
    float4* sv4 = (float4*)sv;
#pragma unroll
    for (int u = 0; u < 2; u++) {
        sq4[t + u * 256] = q4[t + u * 256];
        sv4[t + u * 256] = v4[t + u * 256];
    }
    const float* kp = g_k + base;
#pragma unroll
    for (int u = 0; u < 8; u++) {
        int idx = t + u * 256;
        int r = idx >> 5, d = idx & 31;
        skT[d * 66 + r] = kp[idx];
    }
    const float scale = expf(fminf(ls[h], MAX_LOGIT));
    __syncthreads();

    const float2* skT2 = (const float2*)skT;
    const float2* m2   = (const float2*)(mask + (size_t)w * 4096);

    for (int rr = 0; rr < 8; rr++) {
        const int r = warp * 8 + rr;
        float s0 = 0.f, s1 = 0.f;
        const float4* qrow = (const float4*)(sq + r * 32);
#pragma unroll
        for (int d4 = 0; d4 < 8; d4++) {
            float4 qv = qrow[d4];
            float2 k0 = skT2[(d4 * 4 + 0) * 33 + lane];
            float2 k1 = skT2[(d4 * 4 + 1) * 33 + lane];
            float2 k2 = skT2[(d4 * 4 + 2) * 33 + lane];
            float2 k3 = skT2[(d4 * 4 + 3) * 33 + lane];
            s0 += qv.x * k0.x + qv.y * k1.x + qv.z * k2.x + qv.w * k3.x;
            s1 += qv.x * k0.y + qv.y * k1.y + qv.z * k2.y + qv.w * k3.y;
        }
        float2 mv = m2[r * 32 + lane];
        s0 = s0 * scale + mv.x;
        s1 = s1 * scale + mv.y;

        float mx = fmaxf(s0, s1);
#pragma unroll
        for (int o = 16; o; o >>= 1) mx = fmaxf(mx, __shfl_xor_sync(0xffffffffu, mx, o));
        float e0 = expf(s0 - mx), e1 = expf(s1 - mx);
        float sum = e0 + e1;
#pragma unroll
        for (int o = 16; o; o >>= 1) sum += __shfl_xor_sync(0xffffffffu, sum, o);
        float inv = 1.f / sum;
        ((float2*)pbuf[warp])[lane] = make_float2(e0 * inv, e1 * inv);
        __syncwarp();

        float acc = 0.f;
        const float4* p4 = (const float4*)pbuf[warp];
#pragma unroll
        for (int m4 = 0; m4 < 16; m4++) {
            float4 pv = p4[m4];
            acc += pv.x * sv[(m4 * 4 + 0) * 32 + lane]
                 + pv.y * sv[(m4 * 4 + 1) * 32 + lane]
                 + pv.z * sv[(m4 * 4 + 2) * 32 + lane]
                 + pv.w * sv[(m4 * 4 + 3) * 32 + lane];
        }
        size_t oi = ((size_t)b * 64 + r) * 256 + h * 32 + lane;
        __nv_bfloat16 hh = __float2bfloat16(acc);
        g_aohi[oi] = hh;
        g_aolo[oi] = __float2bfloat16(acc - __bfloat162float(hh));
        __syncwarp();
    }
}

// ---------------------------------------------------------------------------
// Launch
// ---------------------------------------------------------------------------
extern "C" void kernel_launch(void* const* d_in, const int* in_sizes, int n_in,
                              void* d_out, int out_size)
{
    const float* x      = (const float*)d_in[0];
    const float* mask   = (const float*)d_in[1];
    const float* qkv_w  = (const float*)d_in[2];
    const float* qkv_b  = (const float*)d_in[3];
    const float* proj_w = (const float*)d_in[4];
    const float* proj_b = (const float*)d_in[5];
    const float* ls     = (const float*)d_in[6];

    __nv_bfloat16 *p_xhi, *p_xlo, *p_wqhi, *p_wqlo, *p_wphi, *p_wplo, *p_aohi, *p_aolo;
    float *p_qkv;
    cudaGetSymbolAddress((void**)&p_xhi,  g_xhi);
    cudaGetSymbolAddress((void**)&p_xlo,  g_xlo);
    cudaGetSymbolAddress((void**)&p_wqhi, g_wqhi);
    cudaGetSymbolAddress((void**)&p_wqlo, g_wqlo);
    cudaGetSymbolAddress((void**)&p_wphi, g_wphi);
    cudaGetSymbolAddress((void**)&p_wplo, g_wplo);
    cudaGetSymbolAddress((void**)&p_aohi, g_aohi);
    cudaGetSymbolAddress((void**)&p_aolo, g_aolo);
    cudaGetSymbolAddress((void**)&p_qkv,  g_qkv);

    // 0) split inputs / weights to bf16 hi/lo
    split_kernel<<<(NTOK * CDIM / 4 + 255) / 256, 256>>>(x, p_xhi, p_xlo, NTOK * CDIM / 4);
    split_kernel<<<(768 * 256 / 4 + 255) / 256, 256>>>(qkv_w, p_wqhi, p_wqlo, 768 * 256 / 4);
    split_kernel<<<(256 * 256 / 4 + 255) / 256, 256>>>(proj_w, p_wphi, p_wplo, 256 * 256 / 4);

    // 1) QKV GEMM (HMMA): [262144,256] @ [768,256]^T
    gemm_mma_kernel<<<dim3(768 / 128, NTOK / 128), 256>>>(
        p_xhi, p_xlo, p_wqhi, p_wqlo, qkv_b, p_qkv, 768);

    // 2) RoPE + normalize + scatter
    rope_norm_kernel<<<NTOK * 8 / 8, 256>>>();

    // 3) attention per (b, h) — writes bf16 hi/lo attention output
    attn_kernel<<<4096 * 8, 256>>>(mask, ls);

    // 4) proj GEMM (HMMA): [262144,256] @ [256,256]^T -> out
    gemm_mma_kernel<<<dim3(256 / 128, NTOK / 128), 256>>>(
        p_aohi, p_aolo, p_wphi, p_wplo, proj_b, (float*)d_out, 256);
}

// round 8
// speedup vs baseline: 2.3574x; 1.4850x over previous
#include <cuda_runtime.h>
#include <cuda_bf16.h>
#include <math.h>
#include <stdint.h>

// Problem constants
#define NTOK   262144          // 4096 * 64 tokens
#define CDIM   256
#define NH     8
#define HD     32
#define NWIN   64
#define MAX_LOGIT 4.6051701859880914f   // log(100)

// ---------------------------------------------------------------------------
// Scratch (static device globals — allocation-guard safe)
// ---------------------------------------------------------------------------
__device__ __align__(16) __nv_bfloat16 g_xhi[(size_t)NTOK * CDIM];
__device__ __align__(16) __nv_bfloat16 g_xlo[(size_t)NTOK * CDIM];
__device__ __align__(16) __nv_bfloat16 g_wqhi[768 * 256];
__device__ __align__(16) __nv_bfloat16 g_wqlo[768 * 256];
__device__ __align__(16) __nv_bfloat16 g_wphi[256 * 256];
__device__ __align__(16) __nv_bfloat16 g_wplo[256 * 256];
__device__ __align__(16) float g_qkv[(size_t)NTOK * 768];
// q/k/v as bf16 hi/lo, layout [B,H,N,hd]
__device__ __align__(16) __nv_bfloat16 g_qhi[(size_t)NTOK * CDIM];
__device__ __align__(16) __nv_bfloat16 g_qlo[(size_t)NTOK * CDIM];
__device__ __align__(16) __nv_bfloat16 g_khi[(size_t)NTOK * CDIM];
__device__ __align__(16) __nv_bfloat16 g_klo[(size_t)NTOK * CDIM];
__device__ __align__(16) __nv_bfloat16 g_vhi[(size_t)NTOK * CDIM];
__device__ __align__(16) __nv_bfloat16 g_vlo[(size_t)NTOK * CDIM];
__device__ __align__(16) __nv_bfloat16 g_aohi[(size_t)NTOK * CDIM];
__device__ __align__(16) __nv_bfloat16 g_aolo[(size_t)NTOK * CDIM];

// ---------------------------------------------------------------------------
// Helpers (base-target PTX only: cp.async, ldmatrix, mma.sync)
// ---------------------------------------------------------------------------
__device__ __forceinline__ uint32_t smem_u32(const void* p) {
    uint32_t a;
    asm("{ .reg .u64 t; cvta.to.shared.u64 t, %1; cvt.u32.u64 %0, t; }"
        : "=r"(a) : "l"(p));
    return a;
}
#define CP_ASYNC16(dst, src) \
    asm volatile("cp.async.cg.shared.global [%0], [%1], 16;" \
                 :: "r"(dst), "l"(src) : "memory")
#define CP_COMMIT() asm volatile("cp.async.commit_group;" ::: "memory")
#define CP_WAIT(n)  asm volatile("cp.async.wait_group %0;" :: "n"(n) : "memory")

__device__ __forceinline__ void ldsm4(uint32_t& r0, uint32_t& r1,
                                      uint32_t& r2, uint32_t& r3, uint32_t addr) {
    asm volatile("ldmatrix.sync.aligned.m8n8.x4.shared.b16 {%0,%1,%2,%3}, [%4];"
                 : "=r"(r0), "=r"(r1), "=r"(r2), "=r"(r3) : "r"(addr));
}
__device__ __forceinline__ void ldsm4t(uint32_t& r0, uint32_t& r1,
                                       uint32_t& r2, uint32_t& r3, uint32_t addr) {
    asm volatile("ldmatrix.sync.aligned.m8n8.x4.trans.shared.b16 {%0,%1,%2,%3}, [%4];"
                 : "=r"(r0), "=r"(r1), "=r"(r2), "=r"(r3) : "r"(addr));
}
__device__ __forceinline__ void mma_bf16(float& d0, float& d1, float& d2, float& d3,
                                         uint32_t a0, uint32_t a1, uint32_t a2, uint32_t a3,
                                         uint32_t b0, uint32_t b1) {
    asm volatile("mma.sync.aligned.m16n8k16.row.col.f32.bf16.bf16.f32 "
                 "{%0,%1,%2,%3}, {%4,%5,%6,%7}, {%8,%9}, {%0,%1,%2,%3};"
                 : "+f"(d0), "+f"(d1), "+f"(d2), "+f"(d3)
                 : "r"(a0), "r"(a1), "r"(a2), "r"(a3), "r"(b0), "r"(b1));
}
// pack two f32 -> bf16x2 reg (x -> low half, y -> high half)
__device__ __forceinline__ uint32_t pack2(float x, float y) {
    uint32_t d;
    asm("cvt.rn.bf16x2.f32 %0, %1, %2;" : "=r"(d) : "f"(y), "f"(x));
    return d;
}
__device__ __forceinline__ float bf16rt(float x) {
    return __bfloat162float(__float2bfloat16(x));
}

// ---------------------------------------------------------------------------
// fp32 -> (hi, lo) bf16 split
// ---------------------------------------------------------------------------
__global__ __launch_bounds__(256)
void split_kernel(const float* __restrict__ src,
                  __nv_bfloat16* __restrict__ hi,
                  __nv_bfloat16* __restrict__ lo, int n4)
{
    int i = blockIdx.x * 256 + threadIdx.x;
    if (i >= n4) return;
    float4 v = ((const float4*)src)[i];
    __nv_bfloat16 h0 = __float2bfloat16(v.x);
    __nv_bfloat16 h1 = __float2bfloat16(v.y);
    __nv_bfloat16 h2 = __float2bfloat16(v.z);
    __nv_bfloat16 h3 = __float2bfloat16(v.w);
    __nv_bfloat16 l0 = __float2bfloat16(v.x - __bfloat162float(h0));
    __nv_bfloat16 l1 = __float2bfloat16(v.y - __bfloat162float(h1));
    __nv_bfloat16 l2 = __float2bfloat16(v.z - __bfloat162float(h2));
    __nv_bfloat16 l3 = __float2bfloat16(v.w - __bfloat162float(h3));
    __nv_bfloat162 ha = {h0, h1}, hb = {h2, h3};
    __nv_bfloat162 la = {l0, l1}, lb = {l2, l3};
    uint2 ho, loo;
    ho.x = *(uint32_t*)&ha; ho.y = *(uint32_t*)&hb;
    loo.x = *(uint32_t*)&la; loo.y = *(uint32_t*)&lb;
    ((uint2*)hi)[i] = ho;
    ((uint2*)lo)[i] = loo;
}

// ---------------------------------------------------------------------------
// HMMA bf16 split GEMM:  C[M, Ncols] = A[M,256] @ W[Ncols,256]^T + bias
// (unchanged from R6 — tensor 47.3%)
// ---------------------------------------------------------------------------
#define BKB   80          // padded bytes per 32-element bf16 row
#define STG_A 10240       // 128 * 80
#define STG_B 10240

__global__ __launch_bounds__(256)
void gemm_mma_kernel(const __nv_bfloat16* __restrict__ Ahi,
                     const __nv_bfloat16* __restrict__ Alo,
                     const __nv_bfloat16* __restrict__ Whi,
                     const __nv_bfloat16* __restrict__ Wlo,
                     const float* __restrict__ bias,
                     float* __restrict__ C, int Ncols)
{
    __shared__ __align__(16) char smem[2 * STG_A + 2 * STG_B];
    const uint32_t sb  = smem_u32(smem);
    const uint32_t sbA = sb;
    const uint32_t sbB = sb + 2 * STG_A;

    const int t      = threadIdx.x;
    const int lane   = t & 31;
    const int wid    = t >> 5;
    const int warp_m = wid >> 1;
    const int warp_n = wid & 1;
    const int bx     = blockIdx.x;
    const int by     = blockIdx.y;

    const int ldr = t >> 2;
    const int ldc = t & 3;

    float acc[2][8][4];
#pragma unroll
    for (int i = 0; i < 2; i++)
#pragma unroll
        for (int j = 0; j < 8; j++)
#pragma unroll
            for (int q = 0; q < 4; q++) acc[i][j][q] = 0.f;

    const size_t Aoff = (size_t)by * 128 * 256;
    const size_t Woff = (size_t)bx * 128 * 256;

    const uint32_t a_row  = lane & 15;
    const uint32_t a_kh   = (lane >> 4) & 1;
    const uint32_t b_row  = (lane & 7) | ((lane >> 4) << 3);
    const uint32_t b_kh   = (lane >> 3) & 1;

#define LOAD_STAGE(c, s)                                                        \
    do {                                                                        \
        const __nv_bfloat16* As_ = ((c) < 16 ? Ahi : Alo) + Aoff + ((c) & 7) * 32; \
        const __nv_bfloat16* Ws_ = (((c) >= 8 && (c) < 16) ? Wlo : Whi) + Woff + ((c) & 7) * 32; \
        uint32_t dA = sbA + (s) * STG_A;                                        \
        uint32_t dB = sbB + (s) * STG_B;                                        \
        CP_ASYNC16(dA + ldr * BKB + ldc * 16,        As_ + (size_t)ldr * 256 + ldc * 8); \
        CP_ASYNC16(dA + (ldr + 64) * BKB + ldc * 16, As_ + (size_t)(ldr + 64) * 256 + ldc * 8); \
        CP_ASYNC16(dB + ldr * BKB + ldc * 16,        Ws_ + (size_t)ldr * 256 + ldc * 8); \
        CP_ASYNC16(dB + (ldr + 64) * BKB + ldc * 16, Ws_ + (size_t)(ldr + 64) * 256 + ldc * 8); \
        CP_COMMIT();                                                            \
    } while (0)

    LOAD_STAGE(0, 0);

    for (int c = 0; c < 24; ++c) {
        const int s = c & 1;
        if (c + 1 < 24) {
            LOAD_STAGE(c + 1, s ^ 1);
            CP_WAIT(1);
        } else {
            CP_WAIT(0);
        }
        __syncthreads();

        const uint32_t baseA = sbA + s * STG_A + (warp_m * 32 + a_row) * BKB + a_kh * 16;
        const uint32_t baseB = sbB + s * STG_B + (warp_n * 64 + b_row) * BKB + b_kh * 16;

#pragma unroll
        for (int ks = 0; ks < 2; ks++) {
            uint32_t b[4][4];
#pragma unroll
            for (int bn = 0; bn < 4; bn++)
                ldsm4(b[bn][0], b[bn][1], b[bn][2], b[bn][3],
                      baseB + bn * 16 * BKB + ks * 32);
#pragma unroll
            for (int im = 0; im < 2; im++) {
                uint32_t a0, a1, a2, a3;
                ldsm4(a0, a1, a2, a3, baseA + im * 16 * BKB + ks * 32);
#pragma unroll
                for (int bn = 0; bn < 4; bn++) {
                    mma_bf16(acc[im][2 * bn][0], acc[im][2 * bn][1],
                             acc[im][2 * bn][2], acc[im][2 * bn][3],
                             a0, a1, a2, a3, b[bn][0], b[bn][1]);
                    mma_bf16(acc[im][2 * bn + 1][0], acc[im][2 * bn + 1][1],
                             acc[im][2 * bn + 1][2], acc[im][2 * bn + 1][3],
                             a0, a1, a2, a3, b[bn][2], b[bn][3]);
                }
            }
        }
        __syncthreads();
    }

    const int qr = lane >> 2;
    const int qc = (lane & 3) * 2;
#pragma unroll
    for (int im = 0; im < 2; im++) {
        const int m0 = by * 128 + warp_m * 32 + im * 16 + qr;
#pragma unroll
        for (int nn = 0; nn < 8; nn++) {
            const int col = bx * 128 + warp_n * 64 + nn * 8 + qc;
            float2 bv = *(const float2*)(bias + col);
            float2 o0, o1;
            o0.x = acc[im][nn][0] + bv.x;
            o0.y = acc[im][nn][1] + bv.y;
            o1.x = acc[im][nn][2] + bv.x;
            o1.y = acc[im][nn][3] + bv.y;
            *(float2*)(C + (size_t)m0 * Ncols + col)       = o0;
            *(float2*)(C + (size_t)(m0 + 8) * Ncols + col) = o1;
        }
    }
}

// ---------------------------------------------------------------------------
// RoPE + L2-normalize + scatter to [B,H,N,hd] as bf16 hi/lo.
// ---------------------------------------------------------------------------
__global__ __launch_bounds__(256)
void rope_norm_kernel()
{
    const int lane = threadIdx.x & 31;
    const int warp = threadIdx.x >> 5;
    const int gw   = blockIdx.x * 8 + warp;
    const int row  = gw >> 3;
    const int h    = gw & 7;
    const int n    = row & 63;

    size_t base = (size_t)row * 768 + h * 32 + lane;
    float qv = g_qkv[base];
    float kv = g_qkv[base + 256];
    float vv = g_qkv[base + 512];

    const float tpos = (float)n + 0.1f;
    const int   i    = lane & 15;
    float invf = exp2f(-(float)i * 0.8304820237218406f);
    float ang  = tpos * invf;
    float s, c;
    sincosf(ang, &s, &c);

    float qo = __shfl_xor_sync(0xffffffffu, qv, 16);
    float ko = __shfl_xor_sync(0xffffffffu, kv, 16);
    float qr = (lane < 16) ? (qv * c - qo * s) : (qo * s + qv * c);
    float kr = (lane < 16) ? (kv * c - ko * s) : (ko * s + kv * c);

    float nq = qr * qr, nk = kr * kr;
#pragma unroll
    for (int o = 16; o; o >>= 1) {
        nq += __shfl_xor_sync(0xffffffffu, nq, o);
        nk += __shfl_xor_sync(0xffffffffu, nk, o);
    }
    qr /= fmaxf(sqrtf(nq), 1e-12f);
    kr /= fmaxf(sqrtf(nk), 1e-12f);

    const int b = row >> 6;
    size_t oidx = ((size_t)(b * 8 + h) * 64 + n) * 32 + lane;

    __nv_bfloat16 qh = __float2bfloat16(qr);
    __nv_bfloat16 kh = __float2bfloat16(kr);
    __nv_bfloat16 vh = __float2bfloat16(vv);
    g_qhi[oidx] = qh; g_qlo[oidx] = __float2bfloat16(qr - __bfloat162float(qh));
    g_khi[oidx] = kh; g_klo[oidx] = __float2bfloat16(kr - __bfloat162float(kh));
    g_vhi[oidx] = vh; g_vlo[oidx] = __float2bfloat16(vv - __bfloat162float(vh));
}

// ---------------------------------------------------------------------------
// HMMA attention: one block per (b, h), 128 threads = 4 warps.
// Warp w computes query rows [16w, 16w+16).
// S = QK^T (3-term bf16 split), softmax in fragment layout, O = P V
// (3-term split, P split in registers). Output bf16 hi/lo for proj GEMM.
// ---------------------------------------------------------------------------
#define ATS 80                         // padded bytes per 32-bf16 row
#define SM_Q_HI 0
#define SM_Q_LO 5120
#define SM_K_HI 10240
#define SM_K_LO 15360
#define SM_V_HI 20480
#define SM_V_LO 25600
#define SM_MASK 30720                  // 64 rows x 68 floats (272B rows)
#define SM_ATT_TOTAL 48128

__global__ __launch_bounds__(128)
void attn_mma_kernel(const float* __restrict__ mask, const float* __restrict__ ls)
{
    __shared__ __align__(16) char sm[SM_ATT_TOTAL];
    const uint32_t sb = smem_u32(sm);

    const int bid  = blockIdx.x;
    const int b    = bid >> 3;
    const int h    = bid & 7;
    const int w    = b & (NWIN - 1);
    const int t    = threadIdx.x;
    const int lane = t & 31;
    const int warp = t >> 5;

    const size_t base = (size_t)bid * 2048;

    // --- stage q/k/v hi/lo tiles + mask into smem via cp.async ---
    {
        const __nv_bfloat16* srcs[6] = { g_qhi + base, g_qlo + base,
                                         g_khi + base, g_klo + base,
                                         g_vhi + base, g_vlo + base };
        const uint32_t dsts[6] = { sb + SM_Q_HI, sb + SM_Q_LO, sb + SM_K_HI,
                                   sb + SM_K_LO, sb + SM_V_HI, sb + SM_V_LO };
#pragma unroll
        for (int tl = 0; tl < 6; tl++)
#pragma unroll
            for (int u = 0; u < 2; u++) {
                int idx = t + u * 128;          // 0..255 16B chunks
                int row = idx >> 2, c = idx & 3;
                CP_ASYNC16(dsts[tl] + row * ATS + c * 16,
                           srcs[tl] + (size_t)row * 32 + c * 8);
            }
        const float* msrc = mask + (size_t)w * 4096;
#pragma unroll
        for (int u = 0; u < 8; u++) {
            int idx = t + u * 128;              // 0..1023 float4 chunks
            int row = idx >> 4, c4 = idx & 15;
            CP_ASYNC16(sb + SM_MASK + row * 272 + c4 * 16,
                       msrc + (size_t)row * 64 + c4 * 4);
        }
        CP_COMMIT();
        CP_WAIT(0);
    }
    const float scale = __expf(fminf(ls[h], MAX_LOGIT));
    __syncthreads();

    // --- S = Q K^T, 3-term split ---
    const uint32_t a_row = lane & 15;
    const uint32_t a_kh  = (lane >> 4) & 1;
    const uint32_t b_row = (lane & 7) | (((lane >> 4) & 1) << 3);
    const uint32_t b_kh  = (lane >> 3) & 1;

    uint32_t aqh[2][4], aql[2][4];
#pragma unroll
    for (int ks = 0; ks < 2; ks++) {
        uint32_t off = (warp * 16 + a_row) * ATS + a_kh * 16 + ks * 32;
        ldsm4(aqh[ks][0], aqh[ks][1], aqh[ks][2], aqh[ks][3], sb + SM_Q_HI + off);
        ldsm4(aql[ks][0], aql[ks][1], aql[ks][2], aql[ks][3], sb + SM_Q_LO + off);
    }

    float S[8][4];
#pragma unroll
    for (int j = 0; j < 8; j++)
#pragma unroll
        for (int q = 0; q < 4; q++) S[j][q] = 0.f;

#pragma unroll
    for (int ks = 0; ks < 2; ks++)
#pragma unroll
        for (int nh = 0; nh < 4; nh++) {
            uint32_t off = (nh * 16 + b_row) * ATS + b_kh * 16 + ks * 32;
            uint32_t bh[4], bl[4];
            ldsm4(bh[0], bh[1], bh[2], bh[3], sb + SM_K_HI + off);
            ldsm4(bl[0], bl[1], bl[2], bl[3], sb + SM_K_LO + off);
            const int j0 = 2 * nh, j1 = 2 * nh + 1;
            mma_bf16(S[j0][0], S[j0][1], S[j0][2], S[j0][3],
                     aqh[ks][0], aqh[ks][1], aqh[ks][2], aqh[ks][3], bh[0], bh[1]);
            mma_bf16(S[j1][0], S[j1][1], S[j1][2], S[j1][3],
                     aqh[ks][0], aqh[ks][1], aqh[ks][2], aqh[ks][3], bh[2], bh[3]);
            mma_bf16(S[j0][0], S[j0][1], S[j0][2], S[j0][3],
                     aqh[ks][0], aqh[ks][1], aqh[ks][2], aqh[ks][3], bl[0], bl[1]);
            mma_bf16(S[j1][0], S[j1][1], S[j1][2], S[j1][3],
                     aqh[ks][0], aqh[ks][1], aqh[ks][2], aqh[ks][3], bl[2], bl[3]);
            mma_bf16(S[j0][0], S[j0][1], S[j0][2], S[j0][3],
                     aql[ks][0], aql[ks][1], aql[ks][2], aql[ks][3], bh[0], bh[1]);
            mma_bf16(S[j1][0], S[j1][1], S[j1][2], S[j1][3],
                     aql[ks][0], aql[ks][1], aql[ks][2], aql[ks][3], bh[2], bh[3]);
        }

    // --- softmax in fragment layout (row on 4 lanes) ---
    const int qr = lane >> 2;
    const int qc = lane & 3;
    const float* smaskf = (const float*)(sm + SM_MASK);
#pragma unroll
    for (int hf = 0; hf < 2; hf++) {
        const int r = warp * 16 + qr + hf * 8;
        float v[16];
        float mx = -1e30f;
#pragma unroll
        for (int j = 0; j < 8; j++) {
            float2 mv = *(const float2*)(smaskf + r * 68 + j * 8 + qc * 2);
            v[2 * j]     = S[j][2 * hf]     * scale + mv.x;
            v[2 * j + 1] = S[j][2 * hf + 1] * scale + mv.y;
            mx = fmaxf(mx, fmaxf(v[2 * j], v[2 * j + 1]));
        }
        mx = fmaxf(mx, __shfl_xor_sync(0xffffffffu, mx, 1));
        mx = fmaxf(mx, __shfl_xor_sync(0xffffffffu, mx, 2));
        float sum = 0.f;
#pragma unroll
        for (int e = 0; e < 16; e++) { v[e] = __expf(v[e] - mx); sum += v[e]; }
        sum += __shfl_xor_sync(0xffffffffu, sum, 1);
        sum += __shfl_xor_sync(0xffffffffu, sum, 2);
        const float inv = 1.f / sum;
#pragma unroll
        for (int j = 0; j < 8; j++) {
            S[j][2 * hf]     = v[2 * j] * inv;
            S[j][2 * hf + 1] = v[2 * j + 1] * inv;
        }
    }

    // --- O = P V, 3-term split; P split hi/lo in registers ---
    float O[4][4];
#pragma unroll
    for (int j = 0; j < 4; j++)
#pragma unroll
        for (int q = 0; q < 4; q++) O[j][q] = 0.f;

#pragma unroll
    for (int j16 = 0; j16 < 4; j16++) {
        // A fragments from S (C-frag -> A-frag identity)
        uint32_t aph[4], apl[4];
#pragma unroll
        for (int u = 0; u < 2; u++) {          // u=0: n8 tile 2*j16, u=1: +1
            const int jt = 2 * j16 + u;
            float p0 = S[jt][0], p1 = S[jt][1], p2 = S[jt][2], p3 = S[jt][3];
            float h0 = bf16rt(p0), h1 = bf16rt(p1), h2 = bf16rt(p2), h3 = bf16rt(p3);
            aph[2 * u]     = pack2(p0, p1);
            aph[2 * u + 1] = pack2(p2, p3);
            apl[2 * u]     = pack2(p0 - h0, p1 - h1);
            apl[2 * u + 1] = pack2(p2 - h2, p3 - h3);
        }
        // V fragments via ldmatrix.trans
        const uint32_t vrow = j16 * 16 + ((lane >> 3) & 1) * 8 + (lane & 7);
#pragma unroll
        for (int nhh = 0; nhh < 2; nhh++) {
            const uint32_t voff = vrow * ATS + (nhh * 16 + ((lane >> 4) & 1) * 8) * 2;
            uint32_t bh[4], bl[4];
            ldsm4t(bh[0], bh[1], bh[2], bh[3], sb + SM_V_HI + voff);
            ldsm4t(bl[0], bl[1], bl[2], bl[3], sb + SM_V_LO + voff);
            const int n0 = 2 * nhh, n1 = 2 * nhh + 1;
            mma_bf16(O[n0][0], O[n0][1], O[n0][2], O[n0][3],
                     aph[0], aph[1], aph[2], aph[3], bh[0], bh[1]);
            mma_bf16(O[n1][0], O[n1][1], O[n1][2], O[n1][3],
                     aph[0], aph[1], aph[2], aph[3], bh[2], bh[3]);
            mma_bf16(O[n0][0], O[n0][1], O[n0][2], O[n0][3],
                     aph[0], aph[1], aph[2], aph[3], bl[0], bl[1]);
            mma_bf16(O[n1][0], O[n1][1], O[n1][2], O[n1][3],
                     aph[0], aph[1], aph[2], aph[3], bl[2], bl[3]);
            mma_bf16(O[n0][0], O[n0][1], O[n0][2], O[n0][3],
                     apl[0], apl[1], apl[2], apl[3], bh[0], bh[1]);
            mma_bf16(O[n1][0], O[n1][1], O[n1][2], O[n1][3],
                     apl[0], apl[1], apl[2], apl[3], bh[2], bh[3]);
        }
    }

    // --- epilogue: write bf16 hi/lo to [b][n][h*32+d] for proj GEMM ---
#pragma unroll
    for (int nt = 0; nt < 4; nt++)
#pragma unroll
        for (int hf = 0; hf < 2; hf++) {
            const int row = b * 64 + warp * 16 + qr + hf * 8;
            const int col = h * 32 + nt * 8 + qc * 2;
            const size_t oi = (size_t)row * 256 + col;
            float x0 = O[nt][2 * hf], x1 = O[nt][2 * hf + 1];
            float h0 = bf16rt(x0),    h1 = bf16rt(x1);
            *(uint32_t*)(g_aohi + oi) = pack2(x0, x1);
            *(uint32_t*)(g_aolo + oi) = pack2(x0 - h0, x1 - h1);
        }
}

// ---------------------------------------------------------------------------
// Launch
// ---------------------------------------------------------------------------
extern "C" void kernel_launch(void* const* d_in, const int* in_sizes, int n_in,
                              void* d_out, int out_size)
{
    const float* x      = (const float*)d_in[0];
    const float* mask   = (const float*)d_in[1];
    const float* qkv_w  = (const float*)d_in[2];
    const float* qkv_b  = (const float*)d_in[3];
    const float* proj_w = (const float*)d_in[4];
    const float* proj_b = (const float*)d_in[5];
    const float* ls     = (const float*)d_in[6];

    __nv_bfloat16 *p_xhi, *p_xlo, *p_wqhi, *p_wqlo, *p_wphi, *p_wplo, *p_aohi, *p_aolo;
    float *p_qkv;
    cudaGetSymbolAddress((void**)&p_xhi,  g_xhi);
    cudaGetSymbolAddress((void**)&p_xlo,  g_xlo);
    cudaGetSymbolAddress((void**)&p_wqhi, g_wqhi);
    cudaGetSymbolAddress((void**)&p_wqlo, g_wqlo);
    cudaGetSymbolAddress((void**)&p_wphi, g_wphi);
    cudaGetSymbolAddress((void**)&p_wplo, g_wplo);
    cudaGetSymbolAddress((void**)&p_aohi, g_aohi);
    cudaGetSymbolAddress((void**)&p_aolo, g_aolo);
    cudaGetSymbolAddress((void**)&p_qkv,  g_qkv);

    // 0) split inputs / weights to bf16 hi/lo
    split_kernel<<<(NTOK * CDIM / 4 + 255) / 256, 256>>>(x, p_xhi, p_xlo, NTOK * CDIM / 4);
    split_kernel<<<(768 * 256 / 4 + 255) / 256, 256>>>(qkv_w, p_wqhi, p_wqlo, 768 * 256 / 4);
    split_kernel<<<(256 * 256 / 4 + 255) / 256, 256>>>(proj_w, p_wphi, p_wplo, 256 * 256 / 4);

    // 1) QKV GEMM (HMMA): [262144,256] @ [768,256]^T
    gemm_mma_kernel<<<dim3(768 / 128, NTOK / 128), 256>>>(
        p_xhi, p_xlo, p_wqhi, p_wqlo, qkv_b, p_qkv, 768);

    // 2) RoPE + normalize + scatter (bf16 hi/lo)
    rope_norm_kernel<<<NTOK * 8 / 8, 256>>>();

    // 3) attention per (b, h) on tensor cores
    attn_mma_kernel<<<4096 * 8, 128>>>(mask, ls);

    // 4) proj GEMM (HMMA): [262144,256] @ [256,256]^T -> out
    gemm_mma_kernel<<<dim3(256 / 128, NTOK / 128), 256>>>(
        p_aohi, p_aolo, p_wphi, p_wplo, proj_b, (float*)d_out, 256);
}

// round 10
// speedup vs baseline: 2.6756x; 1.1350x over previous
#include <cuda_runtime.h>
#include <cuda_bf16.h>
#include <math.h>
#include <stdint.h>

// Problem constants
#define NTOK   262144          // 4096 * 64 tokens
#define CDIM   256
#define NH     8
#define HD     32
#define NWIN   64
#define MAX_LOGIT 4.6051701859880914f   // log(100)

// ---------------------------------------------------------------------------
// Scratch (static device globals — allocation-guard safe)
// ---------------------------------------------------------------------------
__device__ __align__(16) __nv_bfloat16 g_xhi[(size_t)NTOK * CDIM];
__device__ __align__(16) __nv_bfloat16 g_xlo[(size_t)NTOK * CDIM];
__device__ __align__(16) __nv_bfloat16 g_wqhi[768 * 256];
__device__ __align__(16) __nv_bfloat16 g_wqlo[768 * 256];
__device__ __align__(16) __nv_bfloat16 g_wphi[256 * 256];
__device__ __align__(16) __nv_bfloat16 g_wplo[256 * 256];
__device__ __align__(16) float g_qkv[(size_t)NTOK * 768];
// q/k/v as bf16 hi/lo, layout [B,H,N,hd]
__device__ __align__(16) __nv_bfloat16 g_qhi[(size_t)NTOK * CDIM];
__device__ __align__(16) __nv_bfloat16 g_qlo[(size_t)NTOK * CDIM];
__device__ __align__(16) __nv_bfloat16 g_khi[(size_t)NTOK * CDIM];
__device__ __align__(16) __nv_bfloat16 g_klo[(size_t)NTOK * CDIM];
__device__ __align__(16) __nv_bfloat16 g_vhi[(size_t)NTOK * CDIM];
__device__ __align__(16) __nv_bfloat16 g_vlo[(size_t)NTOK * CDIM];
__device__ __align__(16) __nv_bfloat16 g_aohi[(size_t)NTOK * CDIM];
__device__ __align__(16) __nv_bfloat16 g_aolo[(size_t)NTOK * CDIM];

// ---------------------------------------------------------------------------
// Helpers (base-target PTX only: cp.async, ldmatrix, mma.sync)
// ---------------------------------------------------------------------------
__device__ __forceinline__ uint32_t smem_u32(const void* p) {
    uint32_t a;
    asm("{ .reg .u64 t; cvta.to.shared.u64 t, %1; cvt.u32.u64 %0, t; }"
        : "=r"(a) : "l"(p));
    return a;
}
#define CP_ASYNC16(dst, src) \
    asm volatile("cp.async.cg.shared.global [%0], [%1], 16;" \
                 :: "r"(dst), "l"(src) : "memory")
#define CP_COMMIT() asm volatile("cp.async.commit_group;" ::: "memory")
#define CP_WAIT(n)  asm volatile("cp.async.wait_group %0;" :: "n"(n) : "memory")

__device__ __forceinline__ void ldsm4(uint32_t& r0, uint32_t& r1,
                                      uint32_t& r2, uint32_t& r3, uint32_t addr) {
    asm volatile("ldmatrix.sync.aligned.m8n8.x4.shared.b16 {%0,%1,%2,%3}, [%4];"
                 : "=r"(r0), "=r"(r1), "=r"(r2), "=r"(r3) : "r"(addr));
}
__device__ __forceinline__ void ldsm4t(uint32_t& r0, uint32_t& r1,
                                       uint32_t& r2, uint32_t& r3, uint32_t addr) {
    asm volatile("ldmatrix.sync.aligned.m8n8.x4.trans.shared.b16 {%0,%1,%2,%3}, [%4];"
                 : "=r"(r0), "=r"(r1), "=r"(r2), "=r"(r3) : "r"(addr));
}
__device__ __forceinline__ void mma_bf16(float& d0, float& d1, float& d2, float& d3,
                                         uint32_t a0, uint32_t a1, uint32_t a2, uint32_t a3,
                                         uint32_t b0, uint32_t b1) {
    asm volatile("mma.sync.aligned.m16n8k16.row.col.f32.bf16.bf16.f32 "
                 "{%0,%1,%2,%3}, {%4,%5,%6,%7}, {%8,%9}, {%0,%1,%2,%3};"
                 : "+f"(d0), "+f"(d1), "+f"(d2), "+f"(d3)
                 : "r"(a0), "r"(a1), "r"(a2), "r"(a3), "r"(b0), "r"(b1));
}
// pack two f32 -> bf16x2 reg (x -> low half, y -> high half)
__device__ __forceinline__ uint32_t pack2(float x, float y) {
    uint32_t d;
    asm("cvt.rn.bf16x2.f32 %0, %1, %2;" : "=r"(d) : "f"(y), "f"(x));
    return d;
}
__device__ __forceinline__ float bf16rt(float x) {
    return __bfloat162float(__float2bfloat16(x));
}

// ---------------------------------------------------------------------------
// fp32 -> (hi, lo) bf16 split
// ---------------------------------------------------------------------------
__global__ __launch_bounds__(256)
void split_kernel(const float* __restrict__ src,
                  __nv_bfloat16* __restrict__ hi,
                  __nv_bfloat16* __restrict__ lo, int n4)
{
    int i = blockIdx.x * 256 + threadIdx.x;
    if (i >= n4) return;
    float4 v = ((const float4*)src)[i];
    __nv_bfloat16 h0 = __float2bfloat16(v.x);
    __nv_bfloat16 h1 = __float2bfloat16(v.y);
    __nv_bfloat16 h2 = __float2bfloat16(v.z);
    __nv_bfloat16 h3 = __float2bfloat16(v.w);
    __nv_bfloat16 l0 = __float2bfloat16(v.x - __bfloat162float(h0));
    __nv_bfloat16 l1 = __float2bfloat16(v.y - __bfloat162float(h1));
    __nv_bfloat16 l2 = __float2bfloat16(v.z - __bfloat162float(h2));
    __nv_bfloat16 l3 = __float2bfloat16(v.w - __bfloat162float(h3));
    __nv_bfloat162 ha = {h0, h1}, hb = {h2, h3};
    __nv_bfloat162 la = {l0, l1}, lb = {l2, l3};
    uint2 ho, loo;
    ho.x = *(uint32_t*)&ha; ho.y = *(uint32_t*)&hb;
    loo.x = *(uint32_t*)&la; loo.y = *(uint32_t*)&lb;
    ((uint2*)hi)[i] = ho;
    ((uint2*)lo)[i] = loo;
}

// ---------------------------------------------------------------------------
// HMMA bf16 split GEMM:  C[M, Ncols] = A[M,256] @ W[Ncols,256]^T + bias
// 8 physical K-chunks (BK=32); each stage holds Ahi/Alo/Whi/Wlo tiles and
// computes all 3 split terms (Ahi*Whi + Ahi*Wlo + Alo*Whi) against them.
// Block tile 128x128, 8 warps (4x2), warp tile 32x64, m16n8k16.
// Smem rows padded to 80B (stride-5 chunks) => conflict-free ldmatrix.
// ---------------------------------------------------------------------------
#define BKB    80          // padded bytes per 32-element bf16 row
#define TILE_B 10240       // one 128x32 bf16 tile
#define STG    40960       // 4 tiles: AH | AL | WH | WL
#define GEMM_SMEM (2 * STG)

__global__ __launch_bounds__(256, 2)
void gemm_mma_kernel(const __nv_bfloat16* __restrict__ Ahi,
                     const __nv_bfloat16* __restrict__ Alo,
                     const __nv_bfloat16* __restrict__ Whi,
                     const __nv_bfloat16* __restrict__ Wlo,
                     const float* __restrict__ bias,
                     float* __restrict__ C, int Ncols)
{
    extern __shared__ __align__(16) char smem[];
    const uint32_t sb = smem_u32(smem);

    const int t      = threadIdx.x;
    const int lane   = t & 31;
    const int wid    = t >> 5;
    const int warp_m = wid >> 1;
    const int warp_n = wid & 1;
    const int bx     = blockIdx.x;
    const int by     = blockIdx.y;

    float acc[2][8][4];
#pragma unroll
    for (int i = 0; i < 2; i++)
#pragma unroll
        for (int j = 0; j < 8; j++)
#pragma unroll
            for (int q = 0; q < 4; q++) acc[i][j][q] = 0.f;

    const size_t Aoff = (size_t)by * 128 * 256;
    const size_t Woff = (size_t)bx * 128 * 256;

    const uint32_t a_row  = lane & 15;
    const uint32_t a_kh   = (lane >> 4) & 1;
    const uint32_t b_row  = (lane & 7) | ((lane >> 4) << 3);
    const uint32_t b_kh   = (lane >> 3) & 1;

    // Each tile: 128 rows x 4 16B-chunks = 512 cp.async; 2 per thread.
#define LOAD_STAGE(c, s)                                                         \
    do {                                                                         \
        const __nv_bfloat16* AH_ = Ahi + Aoff + (c) * 32;                        \
        const __nv_bfloat16* AL_ = Alo + Aoff + (c) * 32;                        \
        const __nv_bfloat16* WH_ = Whi + Woff + (c) * 32;                        \
        const __nv_bfloat16* WL_ = Wlo + Woff + (c) * 32;                        \
        const uint32_t d0 = sb + (s) * STG;                                      \
        _Pragma("unroll")                                                        \
        for (int u = 0; u < 2; u++) {                                            \
            int idx = t + u * 256;                                               \
            int row = idx >> 2, cc = idx & 3;                                    \
            uint32_t doff = row * BKB + cc * 16;                                 \
            size_t   soff = (size_t)row * 256 + cc * 8;                          \
            CP_ASYNC16(d0 + doff,              AH_ + soff);                      \
            CP_ASYNC16(d0 + TILE_B + doff,     AL_ + soff);                      \
            CP_ASYNC16(d0 + 2 * TILE_B + doff, WH_ + soff);                      \
            CP_ASYNC16(d0 + 3 * TILE_B + doff, WL_ + soff);                      \
        }                                                                        \
        CP_COMMIT();                                                             \
    } while (0)

    LOAD_STAGE(0, 0);

    for (int c = 0; c < 8; ++c) {
        const int s = c & 1;
        if (c + 1 < 8) {
            LOAD_STAGE(c + 1, s ^ 1);
            CP_WAIT(1);
        } else {
            CP_WAIT(0);
        }
        __syncthreads();

        const uint32_t stg   = sb + s * STG;
        const uint32_t baseA = stg + (warp_m * 32 + a_row) * BKB + a_kh * 16;
        const uint32_t baseB = stg + 2 * TILE_B + (warp_n * 64 + b_row) * BKB + b_kh * 16;

#pragma unroll
        for (int ks = 0; ks < 2; ks++) {
            uint32_t ah[2][4], al[2][4];
#pragma unroll
            for (int im = 0; im < 2; im++) {
                ldsm4(ah[im][0], ah[im][1], ah[im][2], ah[im][3],
                      baseA + im * 16 * BKB + ks * 32);
                ldsm4(al[im][0], al[im][1], al[im][2], al[im][3],
                      baseA + TILE_B + im * 16 * BKB + ks * 32);
            }
#pragma unroll
            for (int bn = 0; bn < 4; bn++) {
                uint32_t bh[4], bl[4];
                ldsm4(bh[0], bh[1], bh[2], bh[3],
                      baseB + bn * 16 * BKB + ks * 32);
                ldsm4(bl[0], bl[1], bl[2], bl[3],
                      baseB + TILE_B + bn * 16 * BKB + ks * 32);
                const int j0 = 2 * bn, j1 = 2 * bn + 1;
#pragma unroll
                for (int im = 0; im < 2; im++) {
                    mma_bf16(acc[im][j0][0], acc[im][j0][1], acc[im][j0][2], acc[im][j0][3],
                             ah[im][0], ah[im][1], ah[im][2], ah[im][3], bh[0], bh[1]);
                    mma_bf16(acc[im][j1][0], acc[im][j1][1], acc[im][j1][2], acc[im][j1][3],
                             ah[im][0], ah[im][1], ah[im][2], ah[im][3], bh[2], bh[3]);
                    mma_bf16(acc[im][j0][0], acc[im][j0][1], acc[im][j0][2], acc[im][j0][3],
                             ah[im][0], ah[im][1], ah[im][2], ah[im][3], bl[0], bl[1]);
                    mma_bf16(acc[im][j1][0], acc[im][j1][1], acc[im][j1][2], acc[im][j1][3],
                             ah[im][0], ah[im][1], ah[im][2], ah[im][3], bl[2], bl[3]);
                    mma_bf16(acc[im][j0][0], acc[im][j0][1], acc[im][j0][2], acc[im][j0][3],
                             al[im][0], al[im][1], al[im][2], al[im][3], bh[0], bh[1]);
                    mma_bf16(acc[im][j1][0], acc[im][j1][1], acc[im][j1][2], acc[im][j1][3],
                             al[im][0], al[im][1], al[im][2], al[im][3], bh[2], bh[3]);
                }
            }
        }
        __syncthreads();
    }

    const int qr = lane >> 2;
    const int qc = (lane & 3) * 2;
#pragma unroll
    for (int im = 0; im < 2; im++) {
        const int m0 = by * 128 + warp_m * 32 + im * 16 + qr;
#pragma unroll
        for (int nn = 0; nn < 8; nn++) {
            const int col = bx * 128 + warp_n * 64 + nn * 8 + qc;
            float2 bv = *(const float2*)(bias + col);
            float2 o0, o1;
            o0.x = acc[im][nn][0] + bv.x;
            o0.y = acc[im][nn][1] + bv.y;
            o1.x = acc[im][nn][2] + bv.x;
            o1.y = acc[im][nn][3] + bv.y;
            *(float2*)(C + (size_t)m0 * Ncols + col)       = o0;
            *(float2*)(C + (size_t)(m0 + 8) * Ncols + col) = o1;
        }
    }
}

// ---------------------------------------------------------------------------
// RoPE + L2-normalize + scatter to [B,H,N,hd] as bf16 hi/lo.
// ---------------------------------------------------------------------------
__global__ __launch_bounds__(256)
void rope_norm_kernel()
{
    const int lane = threadIdx.x & 31;
    const int warp = threadIdx.x >> 5;
    const int gw   = blockIdx.x * 8 + warp;
    const int row  = gw >> 3;
    const int h    = gw & 7;
    const int n    = row & 63;

    size_t base = (size_t)row * 768 + h * 32 + lane;
    float qv = g_qkv[base];
    float kv = g_qkv[base + 256];
    float vv = g_qkv[base + 512];

    const float tpos = (float)n + 0.1f;
    const int   i    = lane & 15;
    float invf = exp2f(-(float)i * 0.8304820237218406f);
    float ang  = tpos * invf;
    float s, c;
    sincosf(ang, &s, &c);

    float qo = __shfl_xor_sync(0xffffffffu, qv, 16);
    float ko = __shfl_xor_sync(0xffffffffu, kv, 16);
    float qr = (lane < 16) ? (qv * c - qo * s) : (qo * s + qv * c);
    float kr = (lane < 16) ? (kv * c - ko * s) : (ko * s + kv * c);

    float nq = qr * qr, nk = kr * kr;
#pragma unroll
    for (int o = 16; o; o >>= 1) {
        nq += __shfl_xor_sync(0xffffffffu, nq, o);
        nk += __shfl_xor_sync(0xffffffffu, nk, o);
    }
    qr /= fmaxf(sqrtf(nq), 1e-12f);
    kr /= fmaxf(sqrtf(nk), 1e-12f);

    const int b = row >> 6;
    size_t oidx = ((size_t)(b * 8 + h) * 64 + n) * 32 + lane;

    __nv_bfloat16 qh = __float2bfloat16(qr);
    __nv_bfloat16 kh = __float2bfloat16(kr);
    __nv_bfloat16 vh = __float2bfloat16(vv);
    g_qhi[oidx] = qh; g_qlo[oidx] = __float2bfloat16(qr - __bfloat162float(qh));
    g_khi[oidx] = kh; g_klo[oidx] = __float2bfloat16(kr - __bfloat162float(kh));
    g_vhi[oidx] = vh; g_vlo[oidx] = __float2bfloat16(vv - __bfloat162float(vh));
}

// ---------------------------------------------------------------------------
// HMMA attention: one block per (b, h), 128 threads = 4 warps.
// ---------------------------------------------------------------------------
#define ATS 80                         // padded bytes per 32-bf16 row
#define SM_Q_HI 0
#define SM_Q_LO 5120
#define SM_K_HI 10240
#define SM_K_LO 15360
#define SM_V_HI 20480
#define SM_V_LO 25600
#define SM_MASK 30720                  // 64 rows x 68 floats (272B rows)
#define SM_ATT_TOTAL 48128

__global__ __launch_bounds__(128)
void attn_mma_kernel(const float* __restrict__ mask, const float* __restrict__ ls)
{
    __shared__ __align__(16) char sm[SM_ATT_TOTAL];
    const uint32_t sb = smem_u32(sm);

    const int bid  = blockIdx.x;
    const int b    = bid >> 3;
    const int h    = bid & 7;
    const int w    = b & (NWIN - 1);
    const int t    = threadIdx.x;
    const int lane = t & 31;
    const int warp = t >> 5;

    const size_t base = (size_t)bid * 2048;

    {
        const __nv_bfloat16* srcs[6] = { g_qhi + base, g_qlo + base,
                                         g_khi + base, g_klo + base,
                                         g_vhi + base, g_vlo + base };
        const uint32_t dsts[6] = { sb + SM_Q_HI, sb + SM_Q_LO, sb + SM_K_HI,
                                   sb + SM_K_LO, sb + SM_V_HI, sb + SM_V_LO };
#pragma unroll
        for (int tl = 0; tl < 6; tl++)
#pragma unroll
            for (int u = 0; u < 2; u++) {
                int idx = t + u * 128;
                int row = idx >> 2, c = idx & 3;
                CP_ASYNC16(dsts[tl] + row * ATS + c * 16,
                           srcs[tl] + (size_t)row * 32 + c * 8);
            }
        const float* msrc = mask + (size_t)w * 4096;
#pragma unroll
        for (int u = 0; u < 8; u++) {
            int idx = t + u * 128;
            int row = idx >> 4, c4 = idx & 15;
            CP_ASYNC16(sb + SM_MASK + row * 272 + c4 * 16,
                       msrc + (size_t)row * 64 + c4 * 4);
        }
        CP_COMMIT();
        CP_WAIT(0);
    }
    const float scale = __expf(fminf(ls[h], MAX_LOGIT));
    __syncthreads();

    const uint32_t a_row = lane & 15;
    const uint32_t a_kh  = (lane >> 4) & 1;
    const uint32_t b_row = (lane & 7) | (((lane >> 4) & 1) << 3);
    const uint32_t b_kh  = (lane >> 3) & 1;

    uint32_t aqh[2][4], aql[2][4];
#pragma unroll
    for (int ks = 0; ks < 2; ks++) {
        uint32_t off = (warp * 16 + a_row) * ATS + a_kh * 16 + ks * 32;
        ldsm4(aqh[ks][0], aqh[ks][1], aqh[ks][2], aqh[ks][3], sb + SM_Q_HI + off);
        ldsm4(aql[ks][0], aql[ks][1], aql[ks][2], aql[ks][3], sb + SM_Q_LO + off);
    }

    float S[8][4];
#pragma unroll
    for (int j = 0; j < 8; j++)
#pragma unroll
        for (int q = 0; q < 4; q++) S[j][q] = 0.f;

#pragma unroll
    for (int ks = 0; ks < 2; ks++)
#pragma unroll
        for (int nh = 0; nh < 4; nh++) {
            uint32_t off = (nh * 16 + b_row) * ATS + b_kh * 16 + ks * 32;
            uint32_t bh[4], bl[4];
            ldsm4(bh[0], bh[1], bh[2], bh[3], sb + SM_K_HI + off);
            ldsm4(bl[0], bl[1], bl[2], bl[3], sb + SM_K_LO + off);
            const int j0 = 2 * nh, j1 = 2 * nh + 1;
            mma_bf16(S[j0][0], S[j0][1], S[j0][2], S[j0][3],
                     aqh[ks][0], aqh[ks][1], aqh[ks][2], aqh[ks][3], bh[0], bh[1]);
            mma_bf16(S[j1][0], S[j1][1], S[j1][2], S[j1][3],
                     aqh[ks][0], aqh[ks][1], aqh[ks][2], aqh[ks][3], bh[2], bh[3]);
            mma_bf16(S[j0][0], S[j0][1], S[j0][2], S[j0][3],
                     aqh[ks][0], aqh[ks][1], aqh[ks][2], aqh[ks][3], bl[0], bl[1]);
            mma_bf16(S[j1][0], S[j1][1], S[j1][2], S[j1][3],
                     aqh[ks][0], aqh[ks][1], aqh[ks][2], aqh[ks][3], bl[2], bl[3]);
            mma_bf16(S[j0][0], S[j0][1], S[j0][2], S[j0][3],
                     aql[ks][0], aql[ks][1], aql[ks][2], aql[ks][3], bh[0], bh[1]);
            mma_bf16(S[j1][0], S[j1][1], S[j1][2], S[j1][3],
                     aql[ks][0], aql[ks][1], aql[ks][2], aql[ks][3], bh[2], bh[3]);
        }

    const int qr = lane >> 2;
    const int qc = lane & 3;
    const float* smaskf = (const float*)(sm + SM_MASK);
#pragma unroll
    for (int hf = 0; hf < 2; hf++) {
        const int r = warp * 16 + qr + hf * 8;
        float v[16];
        float mx = -1e30f;
#pragma unroll
        for (int j = 0; j < 8; j++) {
            float2 mv = *(const float2*)(smaskf + r * 68 + j * 8 + qc * 2);
            v[2 * j]     = S[j][2 * hf]     * scale + mv.x;
            v[2 * j + 1] = S[j][2 * hf + 1] * scale + mv.y;
            mx = fmaxf(mx, fmaxf(v[2 * j], v[2 * j + 1]));
        }
        mx = fmaxf(mx, __shfl_xor_sync(0xffffffffu, mx, 1));
        mx = fmaxf(mx, __shfl_xor_sync(0xffffffffu, mx, 2));
        float sum = 0.f;
#pragma unroll
        for (int e = 0; e < 16; e++) { v[e] = __expf(v[e] - mx); sum += v[e]; }
        sum += __shfl_xor_sync(0xffffffffu, sum, 1);
        sum += __shfl_xor_sync(0xffffffffu, sum, 2);
        const float inv = 1.f / sum;
#pragma unroll
        for (int j = 0; j < 8; j++) {
            S[j][2 * hf]     = v[2 * j] * inv;
            S[j][2 * hf + 1] = v[2 * j + 1] * inv;
        }
    }

    float O[4][4];
#pragma unroll
    for (int j = 0; j < 4; j++)
#pragma unroll
        for (int q = 0; q < 4; q++) O[j][q] = 0.f;

#pragma unroll
    for (int j16 = 0; j16 < 4; j16++) {
        uint32_t aph[4], apl[4];
#pragma unroll
        for (int u = 0; u < 2; u++) {
            const int jt = 2 * j16 + u;
            float p0 = S[jt][0], p1 = S[jt][1], p2 = S[jt][2], p3 = S[jt][3];
            float h0 = bf16rt(p0), h1 = bf16rt(p1), h2 = bf16rt(p2), h3 = bf16rt(p3);
            aph[2 * u]     = pack2(p0, p1);
            aph[2 * u + 1] = pack2(p2, p3);
            apl[2 * u]     = pack2(p0 - h0, p1 - h1);
            apl[2 * u + 1] = pack2(p2 - h2, p3 - h3);
        }
        const uint32_t vrow = j16 * 16 + ((lane >> 3) & 1) * 8 + (lane & 7);
#pragma unroll
        for (int nhh = 0; nhh < 2; nhh++) {
            const uint32_t voff = vrow * ATS + (nhh * 16 + ((lane >> 4) & 1) * 8) * 2;
            uint32_t bh[4], bl[4];
            ldsm4t(bh[0], bh[1], bh[2], bh[3], sb + SM_V_HI + voff);
            ldsm4t(bl[0], bl[1], bl[2], bl[3], sb + SM_V_LO + voff);
            const int n0 = 2 * nhh, n1 = 2 * nhh + 1;
            mma_bf16(O[n0][0], O[n0][1], O[n0][2], O[n0][3],
                     aph[0], aph[1], aph[2], aph[3], bh[0], bh[1]);
            mma_bf16(O[n1][0], O[n1][1], O[n1][2], O[n1][3],
                     aph[0], aph[1], aph[2], aph[3], bh[2], bh[3]);
            mma_bf16(O[n0][0], O[n0][1], O[n0][2], O[n0][3],
                     aph[0], aph[1], aph[2], aph[3], bl[0], bl[1]);
            mma_bf16(O[n1][0], O[n1][1], O[n1][2], O[n1][3],
                     aph[0], aph[1], aph[2], aph[3], bl[2], bl[3]);
            mma_bf16(O[n0][0], O[n0][1], O[n0][2], O[n0][3],
                     apl[0], apl[1], apl[2], apl[3], bh[0], bh[1]);
            mma_bf16(O[n1][0], O[n1][1], O[n1][2], O[n1][3],
                     apl[0], apl[1], apl[2], apl[3], bh[2], bh[3]);
        }
    }

#pragma unroll
    for (int nt = 0; nt < 4; nt++)
#pragma unroll
        for (int hf = 0; hf < 2; hf++) {
            const int row = b * 64 + warp * 16 + qr + hf * 8;
            const int col = h * 32 + nt * 8 + qc * 2;
            const size_t oi = (size_t)row * 256 + col;
            float x0 = O[nt][2 * hf], x1 = O[nt][2 * hf + 1];
            float h0 = bf16rt(x0),    h1 = bf16rt(x1);
            *(uint32_t*)(g_aohi + oi) = pack2(x0, x1);
            *(uint32_t*)(g_aolo + oi) = pack2(x0 - h0, x1 - h1);
        }
}

// ---------------------------------------------------------------------------
// Launch
// ---------------------------------------------------------------------------
extern "C" void kernel_launch(void* const* d_in, const int* in_sizes, int n_in,
                              void* d_out, int out_size)
{
    const float* x      = (const float*)d_in[0];
    const float* mask   = (const float*)d_in[1];
    const float* qkv_w  = (const float*)d_in[2];
    const float* qkv_b  = (const float*)d_in[3];
    const float* proj_w = (const float*)d_in[4];
    const float* proj_b = (const float*)d_in[5];
    const float* ls     = (const float*)d_in[6];

    __nv_bfloat16 *p_xhi, *p_xlo, *p_wqhi, *p_wqlo, *p_wphi, *p_wplo, *p_aohi, *p_aolo;
    float *p_qkv;
    cudaGetSymbolAddress((void**)&p_xhi,  g_xhi);
    cudaGetSymbolAddress((void**)&p_xlo,  g_xlo);
    cudaGetSymbolAddress((void**)&p_wqhi, g_wqhi);
    cudaGetSymbolAddress((void**)&p_wqlo, g_wqlo);
    cudaGetSymbolAddress((void**)&p_wphi, g_wphi);
    cudaGetSymbolAddress((void**)&p_wplo, g_wplo);
    cudaGetSymbolAddress((void**)&p_aohi, g_aohi);
    cudaGetSymbolAddress((void**)&p_aolo, g_aolo);
    cudaGetSymbolAddress((void**)&p_qkv,  g_qkv);

    cudaFuncSetAttribute(gemm_mma_kernel,
                         cudaFuncAttributeMaxDynamicSharedMemorySize, GEMM_SMEM);

    // 0) split inputs / weights to bf16 hi/lo
    split_kernel<<<(NTOK * CDIM / 4 + 255) / 256, 256>>>(x, p_xhi, p_xlo, NTOK * CDIM / 4);
    split_kernel<<<(768 * 256 / 4 + 255) / 256, 256>>>(qkv_w, p_wqhi, p_wqlo, 768 * 256 / 4);
    split_kernel<<<(256 * 256 / 4 + 255) / 256, 256>>>(proj_w, p_wphi, p_wplo, 256 * 256 / 4);

    // 1) QKV GEMM (HMMA): [262144,256] @ [768,256]^T
    gemm_mma_kernel<<<dim3(768 / 128, NTOK / 128), 256, GEMM_SMEM>>>(
        p_xhi, p_xlo, p_wqhi, p_wqlo, qkv_b, p_qkv, 768);

    // 2) RoPE + normalize + scatter (bf16 hi/lo)
    rope_norm_kernel<<<NTOK * 8 / 8, 256>>>();

    // 3) attention per (b, h) on tensor cores
    attn_mma_kernel<<<4096 * 8, 128>>>(mask, ls);

    // 4) proj GEMM (HMMA): [262144,256] @ [256,256]^T -> out
    gemm_mma_kernel<<<dim3(256 / 128, NTOK / 128), 256, GEMM_SMEM>>>(
        p_aohi, p_aolo, p_wphi, p_wplo, proj_b, (float*)d_out, 256);
}

// round 12
// speedup vs baseline: 3.2527x; 1.2157x over previous
#include <cuda_runtime.h>
#include <cuda_bf16.h>
#include <math.h>
#include <stdint.h>

// Problem constants
#define NTOK   262144          // 4096 * 64 tokens
#define CDIM   256
#define NH     8
#define HD     32
#define NWIN   64
#define MAX_LOGIT 4.6051701859880914f   // log(100)

// ---------------------------------------------------------------------------
// Scratch (static device globals — allocation-guard safe)
// ---------------------------------------------------------------------------
__device__ __align__(16) __nv_bfloat16 g_xhi[(size_t)NTOK * CDIM];
__device__ __align__(16) __nv_bfloat16 g_xlo[(size_t)NTOK * CDIM];
__device__ __align__(16) __nv_bfloat16 g_wqhi[768 * 256];
__device__ __align__(16) __nv_bfloat16 g_wqlo[768 * 256];
__device__ __align__(16) __nv_bfloat16 g_wphi[256 * 256];
__device__ __align__(16) __nv_bfloat16 g_wplo[256 * 256];
// q/k/v as bf16 hi/lo, layout [B,H,N,hd]
__device__ __align__(16) __nv_bfloat16 g_qhi[(size_t)NTOK * CDIM];
__device__ __align__(16) __nv_bfloat16 g_qlo[(size_t)NTOK * CDIM];
__device__ __align__(16) __nv_bfloat16 g_khi[(size_t)NTOK * CDIM];
__device__ __align__(16) __nv_bfloat16 g_klo[(size_t)NTOK * CDIM];
__device__ __align__(16) __nv_bfloat16 g_vhi[(size_t)NTOK * CDIM];
__device__ __align__(16) __nv_bfloat16 g_vlo[(size_t)NTOK * CDIM];
__device__ __align__(16) __nv_bfloat16 g_aohi[(size_t)NTOK * CDIM];
__device__ __align__(16) __nv_bfloat16 g_aolo[(size_t)NTOK * CDIM];

// ---------------------------------------------------------------------------
// Helpers (base-target PTX only: cp.async, ldmatrix, mma.sync)
// ---------------------------------------------------------------------------
__device__ __forceinline__ uint32_t smem_u32(const void* p) {
    uint32_t a;
    asm("{ .reg .u64 t; cvta.to.shared.u64 t, %1; cvt.u32.u64 %0, t; }"
        : "=r"(a) : "l"(p));
    return a;
}
#define CP_ASYNC16(dst, src) \
    asm volatile("cp.async.cg.shared.global [%0], [%1], 16;" \
                 :: "r"(dst), "l"(src) : "memory")
#define CP_COMMIT() asm volatile("cp.async.commit_group;" ::: "memory")
#define CP_WAIT(n)  asm volatile("cp.async.wait_group %0;" :: "n"(n) : "memory")

__device__ __forceinline__ void ldsm4(uint32_t& r0, uint32_t& r1,
                                      uint32_t& r2, uint32_t& r3, uint32_t addr) {
    asm volatile("ldmatrix.sync.aligned.m8n8.x4.shared.b16 {%0,%1,%2,%3}, [%4];"
                 : "=r"(r0), "=r"(r1), "=r"(r2), "=r"(r3) : "r"(addr));
}
__device__ __forceinline__ void ldsm4t(uint32_t& r0, uint32_t& r1,
                                       uint32_t& r2, uint32_t& r3, uint32_t addr) {
    asm volatile("ldmatrix.sync.aligned.m8n8.x4.trans.shared.b16 {%0,%1,%2,%3}, [%4];"
                 : "=r"(r0), "=r"(r1), "=r"(r2), "=r"(r3) : "r"(addr));
}
__device__ __forceinline__ void mma_bf16(float& d0, float& d1, float& d2, float& d3,
                                         uint32_t a0, uint32_t a1, uint32_t a2, uint32_t a3,
                                         uint32_t b0, uint32_t b1) {
    asm volatile("mma.sync.aligned.m16n8k16.row.col.f32.bf16.bf16.f32 "
                 "{%0,%1,%2,%3}, {%4,%5,%6,%7}, {%8,%9}, {%0,%1,%2,%3};"
                 : "+f"(d0), "+f"(d1), "+f"(d2), "+f"(d3)
                 : "r"(a0), "r"(a1), "r"(a2), "r"(a3), "r"(b0), "r"(b1));
}
// pack two f32 -> bf16x2 reg (x -> low half, y -> high half)
__device__ __forceinline__ uint32_t pack2(float x, float y) {
    uint32_t d;
    asm("cvt.rn.bf16x2.f32 %0, %1, %2;" : "=r"(d) : "f"(y), "f"(x));
    return d;
}
__device__ __forceinline__ float bf16rt(float x) {
    return __bfloat162float(__float2bfloat16(x));
}

// ---------------------------------------------------------------------------
// fp32 -> (hi, lo) bf16 split
// ---------------------------------------------------------------------------
__global__ __launch_bounds__(256)
void split_kernel(const float* __restrict__ src,
                  __nv_bfloat16* __restrict__ hi,
                  __nv_bfloat16* __restrict__ lo, int n4)
{
    int i = blockIdx.x * 256 + threadIdx.x;
    if (i >= n4) return;
    float4 v = ((const float4*)src)[i];
    __nv_bfloat16 h0 = __float2bfloat16(v.x);
    __nv_bfloat16 h1 = __float2bfloat16(v.y);
    __nv_bfloat16 h2 = __float2bfloat16(v.z);
    __nv_bfloat16 h3 = __float2bfloat16(v.w);
    __nv_bfloat16 l0 = __float2bfloat16(v.x - __bfloat162float(h0));
    __nv_bfloat16 l1 = __float2bfloat16(v.y - __bfloat162float(h1));
    __nv_bfloat16 l2 = __float2bfloat16(v.z - __bfloat162float(h2));
    __nv_bfloat16 l3 = __float2bfloat16(v.w - __bfloat162float(h3));
    __nv_bfloat162 ha = {h0, h1}, hb = {h2, h3};
    __nv_bfloat162 la = {l0, l1}, lb = {l2, l3};
    uint2 ho, loo;
    ho.x = *(uint32_t*)&ha; ho.y = *(uint32_t*)&hb;
    loo.x = *(uint32_t*)&la; loo.y = *(uint32_t*)&lb;
    ((uint2*)hi)[i] = ho;
    ((uint2*)lo)[i] = loo;
}

// ---------------------------------------------------------------------------
// HMMA bf16 split GEMM:  [M,256] @ [Ncols,256]^T + bias
// mode 0: write fp32 C.    mode 1 (QKV): fused RoPE + L2-norm + bf16 hi/lo
// split + scatter to g_{q,k,v}{hi,lo} in [B,H,N,hd] layout.
// Mainloop: term-outermost MMA order over bn-pairs (same-acc spacing = 8).
// ---------------------------------------------------------------------------
#define BKB    80          // padded bytes per 32-element bf16 row
#define TILE_B 10240       // one 128x32 bf16 tile
#define STG    40960       // 4 tiles: AH | AL | WH | WL
#define GEMM_SMEM (2 * STG + 8192)   // + rope table [64][16] float2

__global__ __launch_bounds__(256, 2)
void gemm_mma_kernel(const __nv_bfloat16* __restrict__ Ahi,
                     const __nv_bfloat16* __restrict__ Alo,
                     const __nv_bfloat16* __restrict__ Whi,
                     const __nv_bfloat16* __restrict__ Wlo,
                     const float* __restrict__ bias,
                     float* __restrict__ C, int Ncols, int mode)
{
    extern __shared__ __align__(16) char smem[];
    const uint32_t sb = smem_u32(smem);
    float2* tab = (float2*)(smem + 2 * STG);

    const int t      = threadIdx.x;
    const int lane   = t & 31;
    const int wid    = t >> 5;
    const int warp_m = wid >> 1;
    const int warp_n = wid & 1;
    const int bx     = blockIdx.x;
    const int by     = blockIdx.y;

    // rope cos/sin table (mode 1 only); mainloop's first barrier orders it
    if (mode) {
        for (int idx = t; idx < 1024; idx += 256) {
            int n = idx >> 4, i = idx & 15;
            float ang = ((float)n + 0.1f) * exp2f(-(float)i * 0.8304820237218406f);
            float s, c;
            sincosf(ang, &s, &c);
            tab[idx] = make_float2(c, s);
        }
    }

    float acc[2][8][4];
#pragma unroll
    for (int i = 0; i < 2; i++)
#pragma unroll
        for (int j = 0; j < 8; j++)
#pragma unroll
            for (int q = 0; q < 4; q++) acc[i][j][q] = 0.f;

    const size_t Aoff = (size_t)by * 128 * 256;
    const size_t Woff = (size_t)bx * 128 * 256;

    const uint32_t a_row  = lane & 15;
    const uint32_t a_kh   = (lane >> 4) & 1;
    const uint32_t b_row  = (lane & 7) | ((lane >> 4) << 3);
    const uint32_t b_kh   = (lane >> 3) & 1;

#define LOAD_STAGE(c, s)                                                         \
    do {                                                                         \
        const __nv_bfloat16* AH_ = Ahi + Aoff + (c) * 32;                        \
        const __nv_bfloat16* AL_ = Alo + Aoff + (c) * 32;                        \
        const __nv_bfloat16* WH_ = Whi + Woff + (c) * 32;                        \
        const __nv_bfloat16* WL_ = Wlo + Woff + (c) * 32;                        \
        const uint32_t d0 = sb + (s) * STG;                                      \
        _Pragma("unroll")                                                        \
        for (int u = 0; u < 2; u++) {                                            \
            int idx = t + u * 256;                                               \
            int row = idx >> 2, cc = idx & 3;                                    \
            uint32_t doff = row * BKB + cc * 16;                                 \
            size_t   soff = (size_t)row * 256 + cc * 8;                          \
            CP_ASYNC16(d0 + doff,              AH_ + soff);                      \
            CP_ASYNC16(d0 + TILE_B + doff,     AL_ + soff);                      \
            CP_ASYNC16(d0 + 2 * TILE_B + doff, WH_ + soff);                      \
            CP_ASYNC16(d0 + 3 * TILE_B + doff, WL_ + soff);                      \
        }                                                                        \
        CP_COMMIT();                                                             \
    } while (0)

    LOAD_STAGE(0, 0);

    for (int c = 0; c < 8; ++c) {
        const int s = c & 1;
        if (c + 1 < 8) {
            LOAD_STAGE(c + 1, s ^ 1);
            CP_WAIT(1);
        } else {
            CP_WAIT(0);
        }
        __syncthreads();

        const uint32_t stg   = sb + s * STG;
        const uint32_t baseA = stg + (warp_m * 32 + a_row) * BKB + a_kh * 16;
        const uint32_t baseB = stg + 2 * TILE_B + (warp_n * 64 + b_row) * BKB + b_kh * 16;

#pragma unroll
        for (int ks = 0; ks < 2; ks++) {
            uint32_t ah[2][4], al[2][4];
#pragma unroll
            for (int im = 0; im < 2; im++) {
                ldsm4(ah[im][0], ah[im][1], ah[im][2], ah[im][3],
                      baseA + im * 16 * BKB + ks * 32);
                ldsm4(al[im][0], al[im][1], al[im][2], al[im][3],
                      baseA + TILE_B + im * 16 * BKB + ks * 32);
            }
#pragma unroll
            for (int bnp = 0; bnp < 2; bnp++) {
                uint32_t bh[2][4], bl[2][4];
#pragma unroll
                for (int b2 = 0; b2 < 2; b2++) {
                    const int bn = bnp * 2 + b2;
                    ldsm4(bh[b2][0], bh[b2][1], bh[b2][2], bh[b2][3],
                          baseB + bn * 16 * BKB + ks * 32);
                    ldsm4(bl[b2][0], bl[b2][1], bl[b2][2], bl[b2][3],
                          baseB + TILE_B + bn * 16 * BKB + ks * 32);
                }
                // term HH (8 independent MMAs)
#pragma unroll
                for (int b2 = 0; b2 < 2; b2++) {
                    const int j0 = 2 * (bnp * 2 + b2), j1 = j0 + 1;
#pragma unroll
                    for (int im = 0; im < 2; im++) {
                        mma_bf16(acc[im][j0][0], acc[im][j0][1], acc[im][j0][2], acc[im][j0][3],
                                 ah[im][0], ah[im][1], ah[im][2], ah[im][3], bh[b2][0], bh[b2][1]);
                        mma_bf16(acc[im][j1][0], acc[im][j1][1], acc[im][j1][2], acc[im][j1][3],
                                 ah[im][0], ah[im][1], ah[im][2], ah[im][3], bh[b2][2], bh[b2][3]);
                    }
                }
                // term HL
#pragma unroll
                for (int b2 = 0; b2 < 2; b2++) {
                    const int j0 = 2 * (bnp * 2 + b2), j1 = j0 + 1;
#pragma unroll
                    for (int im = 0; im < 2; im++) {
                        mma_bf16(acc[im][j0][0], acc[im][j0][1], acc[im][j0][2], acc[im][j0][3],
                                 ah[im][0], ah[im][1], ah[im][2], ah[im][3], bl[b2][0], bl[b2][1]);
                        mma_bf16(acc[im][j1][0], acc[im][j1][1], acc[im][j1][2], acc[im][j1][3],
                                 ah[im][0], ah[im][1], ah[im][2], ah[im][3], bl[b2][2], bl[b2][3]);
                    }
                }
                // term LH
#pragma unroll
                for (int b2 = 0; b2 < 2; b2++) {
                    const int j0 = 2 * (bnp * 2 + b2), j1 = j0 + 1;
#pragma unroll
                    for (int im = 0; im < 2; im++) {
                        mma_bf16(acc[im][j0][0], acc[im][j0][1], acc[im][j0][2], acc[im][j0][3],
                                 al[im][0], al[im][1], al[im][2], al[im][3], bh[b2][0], bh[b2][1]);
                        mma_bf16(acc[im][j1][0], acc[im][j1][1], acc[im][j1][2], acc[im][j1][3],
                                 al[im][0], al[im][1], al[im][2], al[im][3], bh[b2][2], bh[b2][3]);
                    }
                }
            }
        }
        __syncthreads();
    }

    const int qr  = lane >> 2;
    const int qc2 = (lane & 3) * 2;

    if (mode == 0) {
        // plain epilogue: bias + fp32 store
#pragma unroll
        for (int im = 0; im < 2; im++) {
            const int m0 = by * 128 + warp_m * 32 + im * 16 + qr;
#pragma unroll
            for (int nn = 0; nn < 8; nn++) {
                const int col = bx * 128 + warp_n * 64 + nn * 8 + qc2;
                float2 bv = *(const float2*)(bias + col);
                float2 o0, o1;
                o0.x = acc[im][nn][0] + bv.x;
                o0.y = acc[im][nn][1] + bv.y;
                o1.x = acc[im][nn][2] + bv.x;
                o1.y = acc[im][nn][3] + bv.y;
                *(float2*)(C + (size_t)m0 * Ncols + col)       = o0;
                *(float2*)(C + (size_t)(m0 + 8) * Ncols + col) = o1;
            }
        }
        return;
    }

    // mode 1: fused RoPE + normalize + bf16 hi/lo split + scatter.
    // type: 0 = q, 1 = k, 2 = v (block-uniform).
    const int type = bx >> 1;
    __nv_bfloat16* ohi = (type == 0) ? g_qhi : (type == 1) ? g_khi : g_vhi;
    __nv_bfloat16* olo = (type == 0) ? g_qlo : (type == 1) ? g_klo : g_vlo;

#pragma unroll
    for (int im = 0; im < 2; im++)
#pragma unroll
        for (int hf = 0; hf < 2; hf++) {
            const int row = by * 128 + warp_m * 32 + im * 16 + hf * 8 + qr;
            const int n   = row & 63;
            const int bb  = row >> 6;
#pragma unroll
            for (int ng = 0; ng < 2; ng++) {
                const int h = (bx & 1) * 4 + warp_n * 2 + ng;
                float v[4][2];
#pragma unroll
                for (int j = 0; j < 4; j++) {
                    const int nn  = ng * 4 + j;
                    const int col = bx * 128 + warp_n * 64 + nn * 8 + qc2;
                    float2 bv = *(const float2*)(bias + col);
                    v[j][0] = acc[im][nn][2 * hf]     + bv.x;
                    v[j][1] = acc[im][nn][2 * hf + 1] + bv.y;
                }
                if (type < 2) {
                    // RoPE: d = j*8+qc2+e (j<2: first half), partner j+2
#pragma unroll
                    for (int j = 0; j < 2; j++)
#pragma unroll
                        for (int e = 0; e < 2; e++) {
                            const int i = j * 8 + qc2 + e;
                            float2 cs = tab[n * 16 + i];
                            float x1 = v[j][e], x2 = v[j + 2][e];
                            v[j][e]     = x1 * cs.x - x2 * cs.y;
                            v[j + 2][e] = x1 * cs.y + x2 * cs.x;
                        }
                    float ss = 0.f;
#pragma unroll
                    for (int j = 0; j < 4; j++)
                        ss += v[j][0] * v[j][0] + v[j][1] * v[j][1];
                    ss += __shfl_xor_sync(0xffffffffu, ss, 1);
                    ss += __shfl_xor_sync(0xffffffffu, ss, 2);
                    const float rn = 1.f / fmaxf(sqrtf(ss), 1e-12f);
#pragma unroll
                    for (int j = 0; j < 4; j++) {
                        v[j][0] *= rn;
                        v[j][1] *= rn;
                    }
                }
                const size_t obase = ((size_t)(bb * 8 + h) * 64 + n) * 32;
#pragma unroll
                for (int j = 0; j < 4; j++) {
                    const int d = j * 8 + qc2;
                    float x0 = v[j][0], x1 = v[j][1];
                    float h0 = bf16rt(x0), h1 = bf16rt(x1);
                    *(uint32_t*)(ohi + obase + d) = pack2(x0, x1);
                    *(uint32_t*)(olo + obase + d) = pack2(x0 - h0, x1 - h1);
                }
            }
        }
}

// ---------------------------------------------------------------------------
// HMMA attention: one block per (b, h), 128 threads = 4 warps.
// ---------------------------------------------------------------------------
#define ATS 80                         // padded bytes per 32-bf16 row
#define SM_Q_HI 0
#define SM_Q_LO 5120
#define SM_K_HI 10240
#define SM_K_LO 15360
#define SM_V_HI 20480
#define SM_V_LO 25600
#define SM_MASK 30720                  // 64 rows x 68 floats (272B rows)
#define SM_ATT_TOTAL 48128

__global__ __launch_bounds__(128)
void attn_mma_kernel(const float* __restrict__ mask, const float* __restrict__ ls)
{
    __shared__ __align__(16) char sm[SM_ATT_TOTAL];
    const uint32_t sb = smem_u32(sm);

    const int bid  = blockIdx.x;
    const int b    = bid >> 3;
    const int h    = bid & 7;
    const int w    = b & (NWIN - 1);
    const int t    = threadIdx.x;
    const int lane = t & 31;
    const int warp = t >> 5;

    const size_t base = (size_t)bid * 2048;

    {
        const __nv_bfloat16* srcs[6] = { g_qhi + base, g_qlo + base,
                                         g_khi + base, g_klo + base,
                                         g_vhi + base, g_vlo + base };
        const uint32_t dsts[6] = { sb + SM_Q_HI, sb + SM_Q_LO, sb + SM_K_HI,
                                   sb + SM_K_LO, sb + SM_V_HI, sb + SM_V_LO };
#pragma unroll
        for (int tl = 0; tl < 6; tl++)
#pragma unroll
            for (int u = 0; u < 2; u++) {
                int idx = t + u * 128;
                int row = idx >> 2, c = idx & 3;
                CP_ASYNC16(dsts[tl] + row * ATS + c * 16,
                           srcs[tl] + (size_t)row * 32 + c * 8);
            }
        const float* msrc = mask + (size_t)w * 4096;
#pragma unroll
        for (int u = 0; u < 8; u++) {
            int idx = t + u * 128;
            int row = idx >> 4, c4 = idx & 15;
            CP_ASYNC16(sb + SM_MASK + row * 272 + c4 * 16,
                       msrc + (size_t)row * 64 + c4 * 4);
        }
        CP_COMMIT();
        CP_WAIT(0);
    }
    const float scale = __expf(fminf(ls[h], MAX_LOGIT));
    __syncthreads();

    const uint32_t a_row = lane & 15;
    const uint32_t a_kh  = (lane >> 4) & 1;
    const uint32_t b_row = (lane & 7) | (((lane >> 4) & 1) << 3);
    const uint32_t b_kh  = (lane >> 3) & 1;

    uint32_t aqh[2][4], aql[2][4];
#pragma unroll
    for (int ks = 0; ks < 2; ks++) {
        uint32_t off = (warp * 16 + a_row) * ATS + a_kh * 16 + ks * 32;
        ldsm4(aqh[ks][0], aqh[ks][1], aqh[ks][2], aqh[ks][3], sb + SM_Q_HI + off);
        ldsm4(aql[ks][0], aql[ks][1], aql[ks][2], aql[ks][3], sb + SM_Q_LO + off);
    }

    float S[8][4];
#pragma unroll
    for (int j = 0; j < 8; j++)
#pragma unroll
        for (int q = 0; q < 4; q++) S[j][q] = 0.f;

#pragma unroll
    for (int ks = 0; ks < 2; ks++)
#pragma unroll
        for (int nh = 0; nh < 4; nh++) {
            uint32_t off = (nh * 16 + b_row) * ATS + b_kh * 16 + ks * 32;
            uint32_t bh[4], bl[4];
            ldsm4(bh[0], bh[1], bh[2], bh[3], sb + SM_K_HI + off);
            ldsm4(bl[0], bl[1], bl[2], bl[3], sb + SM_K_LO + off);
            const int j0 = 2 * nh, j1 = 2 * nh + 1;
            mma_bf16(S[j0][0], S[j0][1], S[j0][2], S[j0][3],
                     aqh[ks][0], aqh[ks][1], aqh[ks][2], aqh[ks][3], bh[0], bh[1]);
            mma_bf16(S[j1][0], S[j1][1], S[j1][2], S[j1][3],
                     aqh[ks][0], aqh[ks][1], aqh[ks][2], aqh[ks][3], bh[2], bh[3]);
            mma_bf16(S[j0][0], S[j0][1], S[j0][2], S[j0][3],
                     aqh[ks][0], aqh[ks][1], aqh[ks][2], aqh[ks][3], bl[0], bl[1]);
            mma_bf16(S[j1][0], S[j1][1], S[j1][2], S[j1][3],
                     aqh[ks][0], aqh[ks][1], aqh[ks][2], aqh[ks][3], bl[2], bl[3]);
            mma_bf16(S[j0][0], S[j0][1], S[j0][2], S[j0][3],
                     aql[ks][0], aql[ks][1], aql[ks][2], aql[ks][3], bh[0], bh[1]);
            mma_bf16(S[j1][0], S[j1][1], S[j1][2], S[j1][3],
                     aql[ks][0], aql[ks][1], aql[ks][2], aql[ks][3], bh[2], bh[3]);
        }

    const int qr = lane >> 2;
    const int qc = lane & 3;
    const float* smaskf = (const float*)(sm + SM_MASK);
#pragma unroll
    for (int hf = 0; hf < 2; hf++) {
        const int r = warp * 16 + qr + hf * 8;
        float v[16];
        float mx = -1e30f;
#pragma unroll
        for (int j = 0; j < 8; j++) {
            float2 mv = *(const float2*)(smaskf + r * 68 + j * 8 + qc * 2);
            v[2 * j]     = S[j][2 * hf]     * scale + mv.x;
            v[2 * j + 1] = S[j][2 * hf + 1] * scale + mv.y;
            mx = fmaxf(mx, fmaxf(v[2 * j], v[2 * j + 1]));
        }
        mx = fmaxf(mx, __shfl_xor_sync(0xffffffffu, mx, 1));
        mx = fmaxf(mx, __shfl_xor_sync(0xffffffffu, mx, 2));
        float sum = 0.f;
#pragma unroll
        for (int e = 0; e < 16; e++) { v[e] = __expf(v[e] - mx); sum += v[e]; }
        sum += __shfl_xor_sync(0xffffffffu, sum, 1);
        sum += __shfl_xor_sync(0xffffffffu, sum, 2);
        const float inv = 1.f / sum;
#pragma unroll
        for (int j = 0; j < 8; j++) {
            S[j][2 * hf]     = v[2 * j] * inv;
            S[j][2 * hf + 1] = v[2 * j + 1] * inv;
        }
    }

    float O[4][4];
#pragma unroll
    for (int j = 0; j < 4; j++)
#pragma unroll
        for (int q = 0; q < 4; q++) O[j][q] = 0.f;

#pragma unroll
    for (int j16 = 0; j16 < 4; j16++) {
        uint32_t aph[4], apl[4];
#pragma unroll
        for (int u = 0; u < 2; u++) {
            const int jt = 2 * j16 + u;
            float p0 = S[jt][0], p1 = S[jt][1], p2 = S[jt][2], p3 = S[jt][3];
            float h0 = bf16rt(p0), h1 = bf16rt(p1), h2 = bf16rt(p2), h3 = bf16rt(p3);
            aph[2 * u]     = pack2(p0, p1);
            aph[2 * u + 1] = pack2(p2, p3);
            apl[2 * u]     = pack2(p0 - h0, p1 - h1);
            apl[2 * u + 1] = pack2(p2 - h2, p3 - h3);
        }
        const uint32_t vrow = j16 * 16 + ((lane >> 3) & 1) * 8 + (lane & 7);
#pragma unroll
        for (int nhh = 0; nhh < 2; nhh++) {
            const uint32_t voff = vrow * ATS + (nhh * 16 + ((lane >> 4) & 1) * 8) * 2;
            uint32_t bh[4], bl[4];
            ldsm4t(bh[0], bh[1], bh[2], bh[3], sb + SM_V_HI + voff);
            ldsm4t(bl[0], bl[1], bl[2], bl[3], sb + SM_V_LO + voff);
            const int n0 = 2 * nhh, n1 = 2 * nhh + 1;
            mma_bf16(O[n0][0], O[n0][1], O[n0][2], O[n0][3],
                     aph[0], aph[1], aph[2], aph[3], bh[0], bh[1]);
            mma_bf16(O[n1][0], O[n1][1], O[n1][2], O[n1][3],
                     aph[0], aph[1], aph[2], aph[3], bh[2], bh[3]);
            mma_bf16(O[n0][0], O[n0][1], O[n0][2], O[n0][3],
                     aph[0], aph[1], aph[2], aph[3], bl[0], bl[1]);
            mma_bf16(O[n1][0], O[n1][1], O[n1][2], O[n1][3],
                     aph[0], aph[1], aph[2], aph[3], bl[2], bl[3]);
            mma_bf16(O[n0][0], O[n0][1], O[n0][2], O[n0][3],
                     apl[0], apl[1], apl[2], apl[3], bh[0], bh[1]);
            mma_bf16(O[n1][0], O[n1][1], O[n1][2], O[n1][3],
                     apl[0], apl[1], apl[2], apl[3], bh[2], bh[3]);
        }
    }

#pragma unroll
    for (int nt = 0; nt < 4; nt++)
#pragma unroll
        for (int hf = 0; hf < 2; hf++) {
            const int row = b * 64 + warp * 16 + qr + hf * 8;
            const int col = h * 32 + nt * 8 + qc * 2;
            const size_t oi = (size_t)row * 256 + col;
            float x0 = O[nt][2 * hf], x1 = O[nt][2 * hf + 1];
            float h0 = bf16rt(x0),    h1 = bf16rt(x1);
            *(uint32_t*)(g_aohi + oi) = pack2(x0, x1);
            *(uint32_t*)(g_aolo + oi) = pack2(x0 - h0, x1 - h1);
        }
}

// ---------------------------------------------------------------------------
// Launch
// ---------------------------------------------------------------------------
extern "C" void kernel_launch(void* const* d_in, const int* in_sizes, int n_in,
                              void* d_out, int out_size)
{
    const float* x      = (const float*)d_in[0];
    const float* mask   = (const float*)d_in[1];
    const float* qkv_w  = (const float*)d_in[2];
    const float* qkv_b  = (const float*)d_in[3];
    const float* proj_w = (const float*)d_in[4];
    const float* proj_b = (const float*)d_in[5];
    const float* ls     = (const float*)d_in[6];

    __nv_bfloat16 *p_xhi, *p_xlo, *p_wqhi, *p_wqlo, *p_wphi, *p_wplo, *p_aohi, *p_aolo;
    cudaGetSymbolAddress((void**)&p_xhi,  g_xhi);
    cudaGetSymbolAddress((void**)&p_xlo,  g_xlo);
    cudaGetSymbolAddress((void**)&p_wqhi, g_wqhi);
    cudaGetSymbolAddress((void**)&p_wqlo, g_wqlo);
    cudaGetSymbolAddress((void**)&p_wphi, g_wphi);
    cudaGetSymbolAddress((void**)&p_wplo, g_wplo);
    cudaGetSymbolAddress((void**)&p_aohi, g_aohi);
    cudaGetSymbolAddress((void**)&p_aolo, g_aolo);

    cudaFuncSetAttribute(gemm_mma_kernel,
                         cudaFuncAttributeMaxDynamicSharedMemorySize, GEMM_SMEM);

    // 0) split inputs / weights to bf16 hi/lo
    split_kernel<<<(NTOK * CDIM / 4 + 255) / 256, 256>>>(x, p_xhi, p_xlo, NTOK * CDIM / 4);
    split_kernel<<<(768 * 256 / 4 + 255) / 256, 256>>>(qkv_w, p_wqhi, p_wqlo, 768 * 256 / 4);
    split_kernel<<<(256 * 256 / 4 + 255) / 256, 256>>>(proj_w, p_wphi, p_wplo, 256 * 256 / 4);

    // 1) QKV GEMM + fused RoPE/norm/split epilogue (mode 1)
    gemm_mma_kernel<<<dim3(768 / 128, NTOK / 128), 256, GEMM_SMEM>>>(
        p_xhi, p_xlo, p_wqhi, p_wqlo, qkv_b, nullptr, 768, 1);

    // 2) attention per (b, h) on tensor cores
    attn_mma_kernel<<<4096 * 8, 128>>>(mask, ls);

    // 3) proj GEMM (mode 0): [262144,256] @ [256,256]^T -> out
    gemm_mma_kernel<<<dim3(256 / 128, NTOK / 128), 256, GEMM_SMEM>>>(
        p_aohi, p_aolo, p_wphi, p_wplo, proj_b, (float*)d_out, 256, 0);
}